// round 5
// baseline (speedup 1.0000x reference)
#include <cuda_runtime.h>
#include <cuda_bf16.h>
#include <math.h>
#include <stdint.h>

typedef unsigned long long u64;
typedef unsigned int u32;

#define BB  4
#define NXX 512
#define NYY 512
#define DVV 32
#define KXX 64
#define KYY 64
#define PI_D 3.14159265358979323846

#define SW128(o) ((o) ^ (((o) >> 3) & 0x70))

__device__ __forceinline__ u32 smem_u32(const void* p) {
    u32 a;
    asm("{ .reg .u64 t; cvta.to.shared.u64 t, %1; cvt.u32.u64 %0, t; }" : "=r"(a) : "l"(p));
    return a;
}
__device__ __forceinline__ void ldsm_x4(u32* r, u32 addr) {
    asm volatile("ldmatrix.sync.aligned.m8n8.x4.shared.b16 {%0,%1,%2,%3}, [%4];"
                 : "=r"(r[0]), "=r"(r[1]), "=r"(r[2]), "=r"(r[3]) : "r"(addr));
}
__device__ __forceinline__ void ldsm_x2(u32* r, u32 addr) {
    asm volatile("ldmatrix.sync.aligned.m8n8.x2.shared.b16 {%0,%1}, [%2];"
                 : "=r"(r[0]), "=r"(r[1]) : "r"(addr));
}
__device__ __forceinline__ void mma_bf16(float* d, const u32* a, const u32* b) {
    asm volatile("mma.sync.aligned.m16n8k16.row.col.f32.bf16.bf16.f32 "
                 "{%0,%1,%2,%3}, {%4,%5,%6,%7}, {%8,%9}, {%0,%1,%2,%3};"
                 : "+f"(d[0]), "+f"(d[1]), "+f"(d[2]), "+f"(d[3])
                 : "r"(a[0]), "r"(a[1]), "r"(a[2]), "r"(a[3]), "r"(b[0]), "r"(b[1]));
}
__device__ __forceinline__ void split_bf16(float v, __nv_bfloat16 &h, __nv_bfloat16 &l) {
    h = __float2bfloat16(v);
    l = __float2bfloat16(v - __bfloat162float(h));
}

// bf16 hi/lo B operands in *smem tile image* layout (SW128-swizzled 128B rows)
// step1: 8 chunks of [64 rows ky][64 k=ny] (8KB each)
__device__ __align__(16) char g_B1h[KYY*NYY*2];
__device__ __align__(16) char g_B1l[KYY*NYY*2];
// step5: [512 rows ny][64 k=ky], 8 passes of 64 rows (8KB each)
__device__ __align__(16) char g_Bth[NYY*KYY*2];
__device__ __align__(16) char g_Btl[NYY*KYY*2];
// step2: 8 chunks of [128 rows (kx real 0..63, kx imag 64..127)][64 k=nx local] (16KB each)
__device__ __align__(16) char g_B2h[2*KXX*NXX*2];
__device__ __align__(16) char g_B2l[2*KXX*NXX*2];
// step4: 8 passes of [64 rows nx local][64 k=kx] (8KB each), real and imag matrices
__device__ __align__(16) char g_B4rh[NXX*KXX*2];
__device__ __align__(16) char g_B4rl[NXX*KXX*2];
__device__ __align__(16) char g_B4ih[NXX*KXX*2];
__device__ __align__(16) char g_B4il[NXX*KXX*2];

// Scratch
__device__ __align__(16) float g_S1 [(size_t)BB*NXX*KYY*DVV];  // [b][nx][ky][dv]
__device__ __align__(16) float g_S2r[(size_t)BB*KXX*KYY*DVV];  // [b][kx][ky][dv]
__device__ __align__(16) float g_S2i[(size_t)BB*KXX*KYY*DVV];
__device__ __align__(16) float g_S3r[(size_t)BB*KYY*KXX*DVV];  // [b][ky][kx][dv]
__device__ __align__(16) float g_S3i[(size_t)BB*KYY*KXX*DVV];
__device__ __align__(16) float g_S4 [(size_t)BB*NXX*KYY*DVV];  // [b][nx][ky][dv]

// ---------------------------------------------------------------------------
// Precompute all transform matrices as bf16 hi/lo swizzled tile images.
// ---------------------------------------------------------------------------
__global__ void k_precompute() {
    int idx = blockIdx.x * blockDim.x + threadIdx.x;
    if (idx >= KXX * NXX) return;
    int k = idx >> 9;          // 0..63
    int n = idx & 511;         // 0..511

    // DCT-II ortho C[k][n]
    double sk = (k == 0) ? sqrt(1.0 / 512.0) : sqrt(2.0 / 512.0);
    int m = (k * (2 * n + 1)) & 2047;
    float Ckn = (float)(sk * cos(PI_D * (double)m / 1024.0));
    {
        __nv_bfloat16 h, l;
        split_bf16(Ckn, h, l);
        u32 byte1 = (u32)(n >> 6) * 8192 + SW128((u32)(k * 128 + (n & 63) * 2));
        *(__nv_bfloat16*)(g_B1h + byte1) = h;
        *(__nv_bfloat16*)(g_B1l + byte1) = l;
        u32 byte5 = SW128((u32)(n * 128 + k * 2));
        *(__nv_bfloat16*)(g_Bth + byte5) = h;
        *(__nv_bfloat16*)(g_Btl + byte5) = l;
    }

    // rfft: F[k][n] = (cos th, -sin th)/sqrt(512)
    int mm = (k * n) & 511;
    double ang = 2.0 * PI_D * (double)mm / 512.0;
    double isq = sqrt(1.0 / 512.0);
    float fr = (float)( cos(ang) * isq);
    float fi = (float)(-sin(ang) * isq);
    float ck = (k == 0) ? 1.0f : 2.0f;

    // step2 B: row kx=k (real), 64+k (imag); chunk = n>>6, col = n&63
    {
        __nv_bfloat16 h, l;
        u32 cb = (u32)(n >> 6) * 16384;
        split_bf16(fr, h, l);
        u32 br = cb + SW128((u32)(k * 128 + (n & 63) * 2));
        *(__nv_bfloat16*)(g_B2h + br) = h;
        *(__nv_bfloat16*)(g_B2l + br) = l;
        split_bf16(fi, h, l);
        u32 bi = cb + SW128((u32)((64 + k) * 128 + (n & 63) * 2));
        *(__nv_bfloat16*)(g_B2h + bi) = h;
        *(__nv_bfloat16*)(g_B2l + bi) = l;
    }
    // step4 B: pass = n>>6, row = n&63, col = k; values ck*fr, ck*fi
    {
        __nv_bfloat16 h, l;
        u32 byte = (u32)(n >> 6) * 8192 + SW128((u32)((n & 63) * 128 + k * 2));
        split_bf16(ck * fr, h, l);
        *(__nv_bfloat16*)(g_B4rh + byte) = h;
        *(__nv_bfloat16*)(g_B4rl + byte) = l;
        split_bf16(ck * fi, h, l);
        *(__nv_bfloat16*)(g_B4ih + byte) = h;
        *(__nv_bfloat16*)(g_B4il + byte) = l;
    }
}

// ---------------------------------------------------------------------------
// Step 1 (HMMA): per (b, nx-quad): D[m=(a,dv)=128][n=ky=64] = sum_ny A·B^T
// K=512 in 8 chunks of 64.  smem: AH@0 AL@16K BH@32K BL@40K  (48KB)
// ---------------------------------------------------------------------------
__global__ __launch_bounds__(128) void k_step1_mma(const float* __restrict__ x) {
    extern __shared__ char smem[];
    u32 sb = smem_u32(smem);
    const u32 sAH = sb, sAL = sb + 16384, sBH = sb + 32768, sBL = sb + 40960;
    int tid = threadIdx.x, w = tid >> 5, lane = tid & 31;
    int nx0 = blockIdx.x * 4, b = blockIdx.y;

    const float* xrow = x + ((size_t)(b * 512 + nx0 + w)) * 512 * 32 + lane;
    int mrow = w * 32 + lane;

    float acc[2][8][4] = {};

    for (int c = 0; c < 8; ++c) {
        {
            const float4* sh = (const float4*)(g_B1h + c * 8192);
            const float4* sl = (const float4*)(g_B1l + c * 8192);
            float4* dh = (float4*)(smem + 32768);
            float4* dl = (float4*)(smem + 40960);
#pragma unroll
            for (int t = 0; t < 4; ++t) { dh[tid + 128 * t] = sh[tid + 128 * t]; dl[tid + 128 * t] = sl[tid + 128 * t]; }
        }
        {
            const float* xc = xrow + (size_t)c * 64 * 32;
#pragma unroll 8
            for (int j2 = 0; j2 < 32; ++j2) {
                float v0 = xc[(2 * j2) * 32];
                float v1 = xc[(2 * j2 + 1) * 32];
                __nv_bfloat16 h0, l0, h1, l1;
                split_bf16(v0, h0, l0);
                split_bf16(v1, h1, l1);
                u32 off = SW128((u32)(mrow * 128 + j2 * 4));
                *(__nv_bfloat162*)(smem + off) = __nv_bfloat162(h0, h1);
                *(__nv_bfloat162*)(smem + 16384 + off) = __nv_bfloat162(l0, l1);
            }
        }
        __syncthreads();

#pragma unroll
        for (int kk = 0; kk < 4; ++kk) {
            u32 ah[2][4], al[2][4], bh[8][2], bl[8][2];
#pragma unroll
            for (int mt = 0; mt < 2; ++mt) {
                u32 row = w * 32 + mt * 16 + (lane & 15);
                u32 blk = kk * 2 + (lane >> 4);
                u32 off = SW128(row * 128 + blk * 16);
                ldsm_x4(ah[mt], sAH + off);
                ldsm_x4(al[mt], sAL + off);
            }
#pragma unroll
            for (int nt = 0; nt < 8; ++nt) {
                u32 row = nt * 8 + (lane & 7);
                u32 blk = kk * 2 + ((lane >> 3) & 1);
                u32 off = SW128(row * 128 + blk * 16);
                ldsm_x2(bh[nt], sBH + off);
                ldsm_x2(bl[nt], sBL + off);
            }
#pragma unroll
            for (int mt = 0; mt < 2; ++mt)
#pragma unroll
                for (int nt = 0; nt < 8; ++nt) {
                    mma_bf16(acc[mt][nt], ah[mt], bh[nt]);
                    mma_bf16(acc[mt][nt], al[mt], bh[nt]);
                    mma_bf16(acc[mt][nt], ah[mt], bl[nt]);
                }
        }
        __syncthreads();
    }

    int g = lane >> 2, t4 = lane & 3;
    float* obase = g_S1 + ((size_t)(b * 512 + nx0 + w)) * 64 * 32;
#pragma unroll
    for (int mt = 0; mt < 2; ++mt)
#pragma unroll
        for (int nt = 0; nt < 8; ++nt) {
            int dv1 = mt * 16 + g, dv2 = dv1 + 8;
            int ky0 = nt * 8 + 2 * t4;
            obase[ky0 * 32 + dv1]       = acc[mt][nt][0];
            obase[(ky0 + 1) * 32 + dv1] = acc[mt][nt][1];
            obase[ky0 * 32 + dv2]       = acc[mt][nt][2];
            obase[(ky0 + 1) * 32 + dv2] = acc[mt][nt][3];
        }
}

// ---------------------------------------------------------------------------
// Step 2 (HMMA): per (b, ky-pair): D[m=(2ky,32dv)=64][n=kx r|i = 64 each]
//  = sum_nx A[m][nx]·B[n][nx].  K=512 in 8 chunks; B r/i halves streamed.
// smem: AH@0(8K) AL@8K BH@16K(8K) BL@24K  (32KB)
// ---------------------------------------------------------------------------
__global__ __launch_bounds__(128) void k_step2_mma() {
    extern __shared__ char smem[];
    u32 sb = smem_u32(smem);
    const u32 sAH = sb, sAL = sb + 8192, sBH = sb + 16384, sBL = sb + 24576;
    int tid = threadIdx.x, w = tid >> 5, lane = tid & 31;
    int ky0 = blockIdx.x * 2, b = blockIdx.y;
    int row = tid & 63, half = tid >> 6;
    const float* s1 = g_S1 + (size_t)b * 512 * 2048 + (size_t)(ky0 + (row >> 5)) * 32 + (row & 31);

    float accr[8][4] = {}, acci[8][4] = {};
    for (int c = 0; c < 8; ++c) {
        // stage A chunk [64 m][64 nx]
        {
            const float* src = s1 + (size_t)(64 * c + half * 32) * 2048;
#pragma unroll 8
            for (int j2 = 0; j2 < 16; ++j2) {
                float v0 = src[(2 * j2) * 2048];
                float v1 = src[(2 * j2 + 1) * 2048];
                __nv_bfloat16 h0, l0, h1, l1;
                split_bf16(v0, h0, l0);
                split_bf16(v1, h1, l1);
                u32 off = SW128((u32)(row * 128 + (half * 32 + 2 * j2) * 2));
                *(__nv_bfloat162*)(smem + off) = __nv_bfloat162(h0, h1);
                *(__nv_bfloat162*)(smem + 8192 + off) = __nv_bfloat162(l0, l1);
            }
        }
        // stage B real half (rows 0..63 of chunk image)
        {
            const float4* sh = (const float4*)(g_B2h + c * 16384);
            const float4* sl = (const float4*)(g_B2l + c * 16384);
            float4* dh = (float4*)(smem + 16384);
            float4* dl = (float4*)(smem + 24576);
#pragma unroll
            for (int t = 0; t < 4; ++t) { dh[tid + 128 * t] = sh[tid + 128 * t]; dl[tid + 128 * t] = sl[tid + 128 * t]; }
        }
        __syncthreads();

        // A fragments for this chunk (reused for both halves)
        u32 ah[4][4], al[4][4];
#pragma unroll
        for (int kk = 0; kk < 4; ++kk) {
            u32 r16 = w * 16 + (lane & 15);
            u32 blk = kk * 2 + (lane >> 4);
            u32 off = SW128(r16 * 128 + blk * 16);
            ldsm_x4(ah[kk], sAH + off);
            ldsm_x4(al[kk], sAL + off);
        }
        // real mma
#pragma unroll
        for (int kk = 0; kk < 4; ++kk)
#pragma unroll
            for (int nt = 0; nt < 8; ++nt) {
                u32 roww = nt * 8 + (lane & 7);
                u32 blk = kk * 2 + ((lane >> 3) & 1);
                u32 off = SW128(roww * 128 + blk * 16);
                u32 bh[2], bl[2];
                ldsm_x2(bh, sBH + off);
                ldsm_x2(bl, sBL + off);
                mma_bf16(accr[nt], ah[kk], bh);
                mma_bf16(accr[nt], al[kk], bh);
                mma_bf16(accr[nt], ah[kk], bl);
            }
        __syncthreads();
        // stage B imag half (rows 64..127 of chunk image)
        {
            const float4* sh = (const float4*)(g_B2h + c * 16384 + 8192);
            const float4* sl = (const float4*)(g_B2l + c * 16384 + 8192);
            float4* dh = (float4*)(smem + 16384);
            float4* dl = (float4*)(smem + 24576);
#pragma unroll
            for (int t = 0; t < 4; ++t) { dh[tid + 128 * t] = sh[tid + 128 * t]; dl[tid + 128 * t] = sl[tid + 128 * t]; }
        }
        __syncthreads();
#pragma unroll
        for (int kk = 0; kk < 4; ++kk)
#pragma unroll
            for (int nt = 0; nt < 8; ++nt) {
                u32 roww = nt * 8 + (lane & 7);
                u32 blk = kk * 2 + ((lane >> 3) & 1);
                u32 off = SW128(roww * 128 + blk * 16);
                u32 bh[2], bl[2];
                ldsm_x2(bh, sBH + off);
                ldsm_x2(bl, sBL + off);
                mma_bf16(acci[nt], ah[kk], bh);
                mma_bf16(acci[nt], al[kk], bh);
                mma_bf16(acci[nt], ah[kk], bl);
            }
        __syncthreads();
    }

    int g = lane >> 2, t4 = lane & 3;
    int m1 = 16 * w + g;
    int kyl = m1 >> 5, dv = m1 & 31;
#pragma unroll
    for (int nt = 0; nt < 8; ++nt) {
        int kx = nt * 8 + 2 * t4;
        size_t base = ((size_t)(b * 64 + kx) * 64 + ky0 + kyl) * 32 + dv;
        g_S2r[base]            = accr[nt][0];
        g_S2r[base + 2048]     = accr[nt][1];
        g_S2r[base + 8]        = accr[nt][2];
        g_S2r[base + 2048 + 8] = accr[nt][3];
        g_S2i[base]            = acci[nt][0];
        g_S2i[base + 2048]     = acci[nt][1];
        g_S2i[base + 8]        = acci[nt][2];
        g_S2i[base + 2048 + 8] = acci[nt][3];
    }
}

// ---------------------------------------------------------------------------
// Step 3 (R2): per-mode complex channel mix, ic split on blockIdx.z
// ---------------------------------------------------------------------------
__global__ __launch_bounds__(256) void k_step3(const float* __restrict__ Rr,
                                               const float* __restrict__ Ri) {
    __shared__ float Xr[4 * 16 * 33], Xi[4 * 16 * 33];
    __shared__ float Sr[4 * 32 * 16], Si[4 * 32 * 16];
    __shared__ float Yr[64 * 4], Yi[64 * 4];
    int kx = blockIdx.x, ky0 = blockIdx.y * 16, ic = blockIdx.z;
    int tid = threadIdx.x;
    int lane = tid & 31, w = tid >> 5;

#pragma unroll
    for (int r = 0; r < 8; ++r) {
        int row = w * 8 + r;
        int e = row >> 4, u = row & 15;
        size_t src = (((size_t)e * KXX + kx) * KYY + ky0 + u) * DVV + lane;
        Xr[(e * 16 + u) * 33 + lane] = g_S2r[src];
        Xi[(e * 16 + u) * 33 + lane] = g_S2i[src];
    }
#pragma unroll
    for (int t = 0; t < 8; ++t) {
        int flat = tid + 256 * t;
        int row = flat >> 4, uu = flat & 15;
        int i4 = row >> 5, j = row & 31;
        size_t src = (((size_t)(ic * 4 + i4) * DVV + j) * KXX + kx) * KYY + ky0 + uu;
        Sr[(i4 * 32 + j) * 16 + uu] = Rr[src];
        Si[(i4 * 32 + j) * 16 + uu] = Ri[src];
    }
    __syncthreads();

    int u = tid & 15, e = (tid >> 4) & 3, ii = tid >> 6;
    float ar = 0.f, ai = 0.f;
#pragma unroll 8
    for (int j = 0; j < 32; ++j) {
        float xr = Xr[(e * 16 + u) * 33 + j];
        float xi = Xi[(e * 16 + u) * 33 + j];
        float rr = Sr[(ii * 32 + j) * 16 + u];
        float ri = Si[(ii * 32 + j) * 16 + u];
        ar = fmaf(rr, xr, ar);
        ar = fmaf(-ri, xi, ar);
        ai = fmaf(rr, xi, ai);
        ai = fmaf(ri, xr, ai);
    }
    Yr[(e * 16 + u) * 4 + ii] = ar;
    Yi[(e * 16 + u) * 4 + ii] = ai;
    __syncthreads();

    if (tid < 128) {
        int row = tid & 63, which = tid >> 6;
        int ee = row >> 4, uu = row & 15;
        float4 v = ((const float4*)(which ? Yi : Yr))[row];
        size_t dst = (((size_t)ee * KYY + ky0 + uu) * KXX + kx) * DVV + ic * 4;
        *(float4*)((which ? g_S3i : g_S3r) + dst) = v;
    }
}

// ---------------------------------------------------------------------------
// Step 4 (HMMA): per (b, ky-pair): D[m=(2ky,32dv)=64][n=nx, 8 passes of 64]
//  = sum_kx Ar[m][kx]·Br[n][kx] + Ai[m][kx]·Bi[n][kx].
// smem: ArH@0 ArL@8K AiH@16K AiL@24K BH@32K BL@40K  (48KB)
// ---------------------------------------------------------------------------
__global__ __launch_bounds__(128) void k_step4_mma() {
    extern __shared__ char smem[];
    u32 sb = smem_u32(smem);
    const u32 sArH = sb, sArL = sb + 8192, sAiH = sb + 16384, sAiL = sb + 24576;
    const u32 sBH = sb + 32768, sBL = sb + 40960;
    int tid = threadIdx.x, w = tid >> 5, lane = tid & 31;
    int ky0 = blockIdx.x * 2, b = blockIdx.y;
    int row = tid & 63, half = tid >> 6;

    // stage A (real and imag), hi/lo split
    {
        size_t base = ((size_t)(b * 64 + ky0 + (row >> 5)) * 64) * 32 + (row & 31);
        const float* s3r = g_S3r + base;
        const float* s3i = g_S3i + base;
#pragma unroll 8
        for (int j2 = 0; j2 < 16; ++j2) {
            int kx = half * 32 + 2 * j2;
            u32 off = SW128((u32)(row * 128 + kx * 2));
            float v0 = s3r[kx * 32], v1 = s3r[(kx + 1) * 32];
            __nv_bfloat16 h0, l0, h1, l1;
            split_bf16(v0, h0, l0);
            split_bf16(v1, h1, l1);
            *(__nv_bfloat162*)(smem + off) = __nv_bfloat162(h0, h1);
            *(__nv_bfloat162*)(smem + 8192 + off) = __nv_bfloat162(l0, l1);
            v0 = s3i[kx * 32]; v1 = s3i[(kx + 1) * 32];
            split_bf16(v0, h0, l0);
            split_bf16(v1, h1, l1);
            *(__nv_bfloat162*)(smem + 16384 + off) = __nv_bfloat162(h0, h1);
            *(__nv_bfloat162*)(smem + 24576 + off) = __nv_bfloat162(l0, l1);
        }
    }
    __syncthreads();

    // preload all A fragments
    u32 arh[4][4], arl[4][4], aih[4][4], ail[4][4];
#pragma unroll
    for (int kk = 0; kk < 4; ++kk) {
        u32 r16 = w * 16 + (lane & 15);
        u32 blk = kk * 2 + (lane >> 4);
        u32 off = SW128(r16 * 128 + blk * 16);
        ldsm_x4(arh[kk], sArH + off);
        ldsm_x4(arl[kk], sArL + off);
        ldsm_x4(aih[kk], sAiH + off);
        ldsm_x4(ail[kk], sAiL + off);
    }

    int g = lane >> 2, t4 = lane & 3;
    int m1 = 16 * w + g;
    int kyl = m1 >> 5, dv = m1 & 31;

    for (int p = 0; p < 8; ++p) {
        __syncthreads();
        // stage B real
        {
            const float4* sh = (const float4*)(g_B4rh + p * 8192);
            const float4* sl = (const float4*)(g_B4rl + p * 8192);
            float4* dh = (float4*)(smem + 32768);
            float4* dl = (float4*)(smem + 40960);
#pragma unroll
            for (int t = 0; t < 4; ++t) { dh[tid + 128 * t] = sh[tid + 128 * t]; dl[tid + 128 * t] = sl[tid + 128 * t]; }
        }
        __syncthreads();
        float acc[8][4] = {};
#pragma unroll
        for (int kk = 0; kk < 4; ++kk)
#pragma unroll
            for (int nt = 0; nt < 8; ++nt) {
                u32 roww = nt * 8 + (lane & 7);
                u32 blk = kk * 2 + ((lane >> 3) & 1);
                u32 off = SW128(roww * 128 + blk * 16);
                u32 bh[2], bl[2];
                ldsm_x2(bh, sBH + off);
                ldsm_x2(bl, sBL + off);
                mma_bf16(acc[nt], arh[kk], bh);
                mma_bf16(acc[nt], arl[kk], bh);
                mma_bf16(acc[nt], arh[kk], bl);
            }
        __syncthreads();
        // stage B imag
        {
            const float4* sh = (const float4*)(g_B4ih + p * 8192);
            const float4* sl = (const float4*)(g_B4il + p * 8192);
            float4* dh = (float4*)(smem + 32768);
            float4* dl = (float4*)(smem + 40960);
#pragma unroll
            for (int t = 0; t < 4; ++t) { dh[tid + 128 * t] = sh[tid + 128 * t]; dl[tid + 128 * t] = sl[tid + 128 * t]; }
        }
        __syncthreads();
#pragma unroll
        for (int kk = 0; kk < 4; ++kk)
#pragma unroll
            for (int nt = 0; nt < 8; ++nt) {
                u32 roww = nt * 8 + (lane & 7);
                u32 blk = kk * 2 + ((lane >> 3) & 1);
                u32 off = SW128(roww * 128 + blk * 16);
                u32 bh[2], bl[2];
                ldsm_x2(bh, sBH + off);
                ldsm_x2(bl, sBL + off);
                mma_bf16(acc[nt], aih[kk], bh);
                mma_bf16(acc[nt], ail[kk], bh);
                mma_bf16(acc[nt], aih[kk], bl);
            }
        // store this pass
#pragma unroll
        for (int nt = 0; nt < 8; ++nt) {
            int nx = p * 64 + nt * 8 + 2 * t4;
            size_t base = ((size_t)(b * 512 + nx) * 64 + ky0 + kyl) * 32 + dv;
            g_S4[base]            = acc[nt][0];
            g_S4[base + 2048]     = acc[nt][1];
            g_S4[base + 8]        = acc[nt][2];
            g_S4[base + 2048 + 8] = acc[nt][3];
        }
    }
}

// ---------------------------------------------------------------------------
// Step 5 (HMMA): per (b, nx-quad): D[m=(a,dv)=128][n=ny], K=ky=64.
// smem: AH@0 AL@16K BH@32K BL@40K  (48KB)
// ---------------------------------------------------------------------------
__global__ __launch_bounds__(128) void k_step5_mma(float* __restrict__ out) {
    extern __shared__ char smem[];
    u32 sb = smem_u32(smem);
    const u32 sAH = sb, sAL = sb + 16384, sBH = sb + 32768, sBL = sb + 40960;
    int tid = threadIdx.x, w = tid >> 5, lane = tid & 31;
    int nx0 = blockIdx.x * 4, b = blockIdx.y;

    {
        int mrow = w * 32 + lane;
        const float* s4row = g_S4 + ((size_t)(b * 512 + nx0 + w)) * 64 * 32 + lane;
#pragma unroll 8
        for (int k2 = 0; k2 < 32; ++k2) {
            float v0 = s4row[(2 * k2) * 32];
            float v1 = s4row[(2 * k2 + 1) * 32];
            __nv_bfloat16 h0, l0, h1, l1;
            split_bf16(v0, h0, l0);
            split_bf16(v1, h1, l1);
            u32 off = SW128((u32)(mrow * 128 + k2 * 4));
            *(__nv_bfloat162*)(smem + off) = __nv_bfloat162(h0, h1);
            *(__nv_bfloat162*)(smem + 16384 + off) = __nv_bfloat162(l0, l1);
        }
    }
    __syncthreads();

    u32 ah[2][4][4], al[2][4][4];
#pragma unroll
    for (int mt = 0; mt < 2; ++mt)
#pragma unroll
        for (int kk = 0; kk < 4; ++kk) {
            u32 row = w * 32 + mt * 16 + (lane & 15);
            u32 blk = kk * 2 + (lane >> 4);
            u32 off = SW128(row * 128 + blk * 16);
            ldsm_x4(ah[mt][kk], sAH + off);
            ldsm_x4(al[mt][kk], sAL + off);
        }

    int g = lane >> 2, t4 = lane & 3;
    float* obase = out + ((size_t)(b * 512 + nx0 + w)) * 512 * 32;

    for (int p = 0; p < 8; ++p) {
        __syncthreads();
        {
            const float4* sh = (const float4*)(g_Bth + p * 8192);
            const float4* sl = (const float4*)(g_Btl + p * 8192);
            float4* dh = (float4*)(smem + 32768);
            float4* dl = (float4*)(smem + 40960);
#pragma unroll
            for (int t = 0; t < 4; ++t) { dh[tid + 128 * t] = sh[tid + 128 * t]; dl[tid + 128 * t] = sl[tid + 128 * t]; }
        }
        __syncthreads();

#pragma unroll
        for (int nt = 0; nt < 8; ++nt) {
            u32 bh[4][2], bl[4][2];
#pragma unroll
            for (int kk = 0; kk < 4; ++kk) {
                u32 row = nt * 8 + (lane & 7);
                u32 blk = kk * 2 + ((lane >> 3) & 1);
                u32 off = SW128(row * 128 + blk * 16);
                ldsm_x2(bh[kk], sBH + off);
                ldsm_x2(bl[kk], sBL + off);
            }
            float acc[2][4] = {};
#pragma unroll
            for (int kk = 0; kk < 4; ++kk)
#pragma unroll
                for (int mt = 0; mt < 2; ++mt) {
                    mma_bf16(acc[mt], ah[mt][kk], bh[kk]);
                    mma_bf16(acc[mt], al[mt][kk], bh[kk]);
                    mma_bf16(acc[mt], ah[mt][kk], bl[kk]);
                }
#pragma unroll
            for (int mt = 0; mt < 2; ++mt) {
                int dv1 = mt * 16 + g, dv2 = dv1 + 8;
                int ny0 = p * 64 + nt * 8 + 2 * t4;
                obase[(size_t)ny0 * 32 + dv1]       = acc[mt][0];
                obase[(size_t)(ny0 + 1) * 32 + dv1] = acc[mt][1];
                obase[(size_t)ny0 * 32 + dv2]       = acc[mt][2];
                obase[(size_t)(ny0 + 1) * 32 + dv2] = acc[mt][3];
            }
        }
    }
}

// ---------------------------------------------------------------------------
extern "C" void kernel_launch(void* const* d_in, const int* in_sizes, int n_in,
                              void* d_out, int out_size) {
    const float* x  = (const float*)d_in[0];
    const float* Rr = (const float*)d_in[1];
    const float* Ri = (const float*)d_in[2];
    float* out = (float*)d_out;

    k_precompute<<<128, 256>>>();
    k_step1_mma<<<dim3(128, BB), 128, 49152>>>(x);
    k_step2_mma<<<dim3(32, BB), 128, 32768>>>();
    k_step3<<<dim3(KXX, KYY / 16, 8), 256>>>(Rr, Ri);
    k_step4_mma<<<dim3(32, BB), 128, 49152>>>();
    k_step5_mma<<<dim3(128, BB), 128, 49152>>>(out);
}

// round 6
// speedup vs baseline: 1.3240x; 1.3240x over previous
#include <cuda_runtime.h>
#include <cuda_bf16.h>
#include <math.h>
#include <stdint.h>

typedef unsigned long long u64;
typedef unsigned int u32;

#define BB  4
#define NXX 512
#define NYY 512
#define DVV 32
#define KXX 64
#define KYY 64
#define PI_F 3.14159265358979323846f

#define SW128(o) ((o) ^ (((o) >> 3) & 0x70))

__device__ __forceinline__ u32 smem_u32(const void* p) {
    u32 a;
    asm("{ .reg .u64 t; cvta.to.shared.u64 t, %1; cvt.u32.u64 %0, t; }" : "=r"(a) : "l"(p));
    return a;
}
__device__ __forceinline__ void ldsm_x4(u32* r, u32 addr) {
    asm volatile("ldmatrix.sync.aligned.m8n8.x4.shared.b16 {%0,%1,%2,%3}, [%4];"
                 : "=r"(r[0]), "=r"(r[1]), "=r"(r[2]), "=r"(r[3]) : "r"(addr));
}
__device__ __forceinline__ void ldsm_x2(u32* r, u32 addr) {
    asm volatile("ldmatrix.sync.aligned.m8n8.x2.shared.b16 {%0,%1}, [%2];"
                 : "=r"(r[0]), "=r"(r[1]) : "r"(addr));
}
__device__ __forceinline__ void mma_bf16(float* d, const u32* a, const u32* b) {
    asm volatile("mma.sync.aligned.m16n8k16.row.col.f32.bf16.bf16.f32 "
                 "{%0,%1,%2,%3}, {%4,%5,%6,%7}, {%8,%9}, {%0,%1,%2,%3};"
                 : "+f"(d[0]), "+f"(d[1]), "+f"(d[2]), "+f"(d[3])
                 : "r"(a[0]), "r"(a[1]), "r"(a[2]), "r"(a[3]), "r"(b[0]), "r"(b[1]));
}
// RN split (precompute only)
__device__ __forceinline__ void split_bf16(float v, __nv_bfloat16 &h, __nv_bfloat16 &l) {
    h = __float2bfloat16(v);
    l = __float2bfloat16(v - __bfloat162float(h));
}
// Fast truncation split for a pair of fp32: hp = packed truncated-bf16 pair (1 PRMT),
// lp = packed bf16 residuals. v - h exact; dropped AlBl ~ 2^-17.
__device__ __forceinline__ void split_pair(float v0, float v1, u32 &hp, u32 &lp) {
    u32 u0 = __float_as_uint(v0), u1 = __float_as_uint(v1);
    hp = __byte_perm(u0, u1, 0x7632);
    float l0 = v0 - __uint_as_float(u0 & 0xFFFF0000u);
    float l1 = v1 - __uint_as_float(u1 & 0xFFFF0000u);
    asm("cvt.rn.bf16x2.f32 %0, %1, %2;" : "=r"(lp) : "f"(l1), "f"(l0));
}

// fp32 matrices for scalar steps 2/4
__device__ __align__(16) float g_Ftr[NXX*KXX];   // [n][k]
__device__ __align__(16) float g_Fti[NXX*KXX];
__device__ __align__(16) float g_Gr [KXX*NXX];   // [k][n]
__device__ __align__(16) float g_Gi [KXX*NXX];

// bf16 hi/lo B operands in smem tile image layout (SW128 rows)
// step1: 8 chunks of [64 rows ky][64 k=ny] (8KB each)
__device__ __align__(16) char g_B1h[KYY*NYY*2];
__device__ __align__(16) char g_B1l[KYY*NYY*2];
// step5: [512 rows ny][64 k=ky], 8 passes of 64 rows (8KB each)
__device__ __align__(16) char g_Bth[NYY*KYY*2];
__device__ __align__(16) char g_Btl[NYY*KYY*2];

// Scratch
__device__ __align__(16) float g_S1 [(size_t)BB*NXX*KYY*DVV];  // [b][nx][ky][dv]
__device__ __align__(16) float g_S2r[(size_t)BB*KXX*KYY*DVV];  // [b][kx][ky][dv]
__device__ __align__(16) float g_S2i[(size_t)BB*KXX*KYY*DVV];
__device__ __align__(16) float g_S3r[(size_t)BB*KYY*KXX*DVV];  // [b][ky][kx][dv]
__device__ __align__(16) float g_S3i[(size_t)BB*KYY*KXX*DVV];
__device__ __align__(16) float g_S4 [(size_t)BB*NXX*KYY*DVV];  // [b][nx][ky][dv]

// ---------------------------------------------------------------------------
// Precompute (fp32 trig — matrices need only ~1e-7).
// ---------------------------------------------------------------------------
__global__ void k_precompute() {
    int idx = blockIdx.x * blockDim.x + threadIdx.x;
    if (idx >= KXX * NXX) return;
    int k = idx >> 9;          // 0..63
    int n = idx & 511;         // 0..511

    float sk = (k == 0) ? sqrtf(1.0f / 512.0f) : sqrtf(2.0f / 512.0f);
    int m = (k * (2 * n + 1)) & 2047;
    float mm1 = (float)((m > 1024) ? (2048 - m) : m);   // cos symmetric
    float Ckn = sk * cosf(PI_F * mm1 / 1024.0f);
    {
        __nv_bfloat16 h, l;
        split_bf16(Ckn, h, l);
        u32 byte1 = (u32)(n >> 6) * 8192 + SW128((u32)(k * 128 + (n & 63) * 2));
        *(__nv_bfloat16*)(g_B1h + byte1) = h;
        *(__nv_bfloat16*)(g_B1l + byte1) = l;
        u32 byte5 = SW128((u32)(n * 128 + k * 2));
        *(__nv_bfloat16*)(g_Bth + byte5) = h;
        *(__nv_bfloat16*)(g_Btl + byte5) = l;
    }

    int mm = (k * n) & 511;
    float ang = 2.0f * PI_F * (float)mm / 512.0f;
    float isq = sqrtf(1.0f / 512.0f);
    float s, c;
    sincosf(ang, &s, &c);
    float fr = c * isq;
    float fi = -s * isq;
    g_Ftr[n * 64 + k] = fr;
    g_Fti[n * 64 + k] = fi;
    float ck = (k == 0) ? 1.0f : 2.0f;
    g_Gr[k * 512 + n] = ck * fr;
    g_Gi[k * 512 + n] = ck * fi;
}

// ---------------------------------------------------------------------------
// Step 1 (HMMA): per (b, nx-quad): D[m=(a,dv)=128][n=ky=64] = sum_ny A·B^T
// K=512 in 8 chunks of 64.  smem: AH@0 AL@16K BH@32K BL@40K  (48KB)
// ---------------------------------------------------------------------------
__global__ __launch_bounds__(128) void k_step1_mma(const float* __restrict__ x) {
    extern __shared__ char smem[];
    u32 sb = smem_u32(smem);
    const u32 sAH = sb, sAL = sb + 16384, sBH = sb + 32768, sBL = sb + 40960;
    int tid = threadIdx.x, w = tid >> 5, lane = tid & 31;
    int nx0 = blockIdx.x * 4, b = blockIdx.y;

    const float* xrow = x + ((size_t)(b * 512 + nx0 + w)) * 512 * 32 + lane;
    int mrow = w * 32 + lane;

    float acc[2][8][4] = {};

    for (int c = 0; c < 8; ++c) {
        {
            const float4* sh = (const float4*)(g_B1h + c * 8192);
            const float4* sl = (const float4*)(g_B1l + c * 8192);
            float4* dh = (float4*)(smem + 32768);
            float4* dl = (float4*)(smem + 40960);
#pragma unroll
            for (int t = 0; t < 4; ++t) { dh[tid + 128 * t] = sh[tid + 128 * t]; dl[tid + 128 * t] = sl[tid + 128 * t]; }
        }
        {
            const float* xc = xrow + (size_t)c * 64 * 32;
#pragma unroll 8
            for (int j2 = 0; j2 < 32; ++j2) {
                float v0 = xc[(2 * j2) * 32];
                float v1 = xc[(2 * j2 + 1) * 32];
                u32 hp, lp;
                split_pair(v0, v1, hp, lp);
                u32 off = SW128((u32)(mrow * 128 + j2 * 4));
                *(u32*)(smem + off) = hp;
                *(u32*)(smem + 16384 + off) = lp;
            }
        }
        __syncthreads();

#pragma unroll
        for (int kk = 0; kk < 4; ++kk) {
            u32 ah[2][4], al[2][4], bh[8][2], bl[8][2];
#pragma unroll
            for (int mt = 0; mt < 2; ++mt) {
                u32 row = w * 32 + mt * 16 + (lane & 15);
                u32 blk = kk * 2 + (lane >> 4);
                u32 off = SW128(row * 128 + blk * 16);
                ldsm_x4(ah[mt], sAH + off);
                ldsm_x4(al[mt], sAL + off);
            }
#pragma unroll
            for (int nt = 0; nt < 8; ++nt) {
                u32 row = nt * 8 + (lane & 7);
                u32 blk = kk * 2 + ((lane >> 3) & 1);
                u32 off = SW128(row * 128 + blk * 16);
                ldsm_x2(bh[nt], sBH + off);
                ldsm_x2(bl[nt], sBL + off);
            }
#pragma unroll
            for (int mt = 0; mt < 2; ++mt)
#pragma unroll
                for (int nt = 0; nt < 8; ++nt) {
                    mma_bf16(acc[mt][nt], ah[mt], bh[nt]);
                    mma_bf16(acc[mt][nt], al[mt], bh[nt]);
                    mma_bf16(acc[mt][nt], ah[mt], bl[nt]);
                }
        }
        __syncthreads();
    }

    int g = lane >> 2, t4 = lane & 3;
    float* obase = g_S1 + ((size_t)(b * 512 + nx0 + w)) * 64 * 32;
#pragma unroll
    for (int mt = 0; mt < 2; ++mt)
#pragma unroll
        for (int nt = 0; nt < 8; ++nt) {
            int dv1 = mt * 16 + g, dv2 = dv1 + 8;
            int ky0 = nt * 8 + 2 * t4;
            obase[ky0 * 32 + dv1]       = acc[mt][nt][0];
            obase[(ky0 + 1) * 32 + dv1] = acc[mt][nt][1];
            obase[ky0 * 32 + dv2]       = acc[mt][nt][2];
            obase[(ky0 + 1) * 32 + dv2] = acc[mt][nt][3];
        }
}

// ---------------------------------------------------------------------------
// Step 2 (scalar, R1): S2 = rFFT-X of S1
// ---------------------------------------------------------------------------
__global__ __launch_bounds__(128) void k_step2() {
    __shared__ float Ar[32 * 64], Ai[32 * 64], Bs[32 * 32];
    int ky = blockIdx.x, b = blockIdx.y;
    int tid = threadIdx.x;
    int dg = tid & 7, kg = tid >> 3;
    const float* s1base = g_S1 + (size_t)b * NXX * KYY * DVV + (size_t)ky * DVV;

    float accr[4][4] = {}, acci[4][4] = {};
    for (int c = 0; c < 16; ++c) {
        const float4* sar = (const float4*)(g_Ftr + c * 32 * 64);
        const float4* sai = (const float4*)(g_Fti + c * 32 * 64);
#pragma unroll
        for (int t = 0; t < 4; ++t) {
            ((float4*)Ar)[tid + 128 * t] = sar[tid + 128 * t];
            ((float4*)Ai)[tid + 128 * t] = sai[tid + 128 * t];
        }
#pragma unroll
        for (int t = 0; t < 2; ++t) {
            int j = tid + 128 * t;
            int nn = j >> 3, q = j & 7;
            ((float4*)Bs)[j] = *(const float4*)(s1base + (size_t)(c * 32 + nn) * KYY * DVV + 4 * q);
        }
        __syncthreads();
#pragma unroll 8
        for (int nn = 0; nn < 32; ++nn) {
            float4 ar = *(const float4*)(Ar + nn * 64 + 4 * kg);
            float4 ai = *(const float4*)(Ai + nn * 64 + 4 * kg);
            float4 v  = *(const float4*)(Bs + nn * 32 + 4 * dg);
            float arr[4] = {ar.x, ar.y, ar.z, ar.w};
            float aii[4] = {ai.x, ai.y, ai.z, ai.w};
            float vv[4]  = {v.x, v.y, v.z, v.w};
#pragma unroll
            for (int r = 0; r < 4; ++r)
#pragma unroll
                for (int q = 0; q < 4; ++q) {
                    accr[r][q] = fmaf(arr[r], vv[q], accr[r][q]);
                    acci[r][q] = fmaf(aii[r], vv[q], acci[r][q]);
                }
        }
        __syncthreads();
    }
#pragma unroll
    for (int r = 0; r < 4; ++r) {
        int kx = 4 * kg + r;
        size_t dst = (((size_t)b * KXX + kx) * KYY + ky) * DVV + 4 * dg;
        *(float4*)(g_S2r + dst) = make_float4(accr[r][0], accr[r][1], accr[r][2], accr[r][3]);
        *(float4*)(g_S2i + dst) = make_float4(acci[r][0], acci[r][1], acci[r][2], acci[r][3]);
    }
}

// ---------------------------------------------------------------------------
// Step 3 (R2): per-mode complex channel mix, ic split on blockIdx.z
// ---------------------------------------------------------------------------
__global__ __launch_bounds__(256) void k_step3(const float* __restrict__ Rr,
                                               const float* __restrict__ Ri) {
    __shared__ float Xr[4 * 16 * 33], Xi[4 * 16 * 33];
    __shared__ float Sr[4 * 32 * 16], Si[4 * 32 * 16];
    __shared__ float Yr[64 * 4], Yi[64 * 4];
    int kx = blockIdx.x, ky0 = blockIdx.y * 16, ic = blockIdx.z;
    int tid = threadIdx.x;
    int lane = tid & 31, w = tid >> 5;

#pragma unroll
    for (int r = 0; r < 8; ++r) {
        int row = w * 8 + r;
        int e = row >> 4, u = row & 15;
        size_t src = (((size_t)e * KXX + kx) * KYY + ky0 + u) * DVV + lane;
        Xr[(e * 16 + u) * 33 + lane] = g_S2r[src];
        Xi[(e * 16 + u) * 33 + lane] = g_S2i[src];
    }
#pragma unroll
    for (int t = 0; t < 8; ++t) {
        int flat = tid + 256 * t;
        int row = flat >> 4, uu = flat & 15;
        int i4 = row >> 5, j = row & 31;
        size_t src = (((size_t)(ic * 4 + i4) * DVV + j) * KXX + kx) * KYY + ky0 + uu;
        Sr[(i4 * 32 + j) * 16 + uu] = Rr[src];
        Si[(i4 * 32 + j) * 16 + uu] = Ri[src];
    }
    __syncthreads();

    int u = tid & 15, e = (tid >> 4) & 3, ii = tid >> 6;
    float ar = 0.f, ai = 0.f;
#pragma unroll 8
    for (int j = 0; j < 32; ++j) {
        float xr = Xr[(e * 16 + u) * 33 + j];
        float xi = Xi[(e * 16 + u) * 33 + j];
        float rr = Sr[(ii * 32 + j) * 16 + u];
        float ri = Si[(ii * 32 + j) * 16 + u];
        ar = fmaf(rr, xr, ar);
        ar = fmaf(-ri, xi, ar);
        ai = fmaf(rr, xi, ai);
        ai = fmaf(ri, xr, ai);
    }
    Yr[(e * 16 + u) * 4 + ii] = ar;
    Yi[(e * 16 + u) * 4 + ii] = ai;
    __syncthreads();

    if (tid < 128) {
        int row = tid & 63, which = tid >> 6;
        int ee = row >> 4, uu = row & 15;
        float4 v = ((const float4*)(which ? Yi : Yr))[row];
        size_t dst = (((size_t)ee * KYY + ky0 + uu) * KXX + kx) * DVV + ic * 4;
        *(float4*)((which ? g_S3i : g_S3r) + dst) = v;
    }
}

// ---------------------------------------------------------------------------
// Step 4 (scalar, R1): irFFT-X truncated
// ---------------------------------------------------------------------------
__global__ __launch_bounds__(128) void k_step4() {
    __shared__ float Agr[32 * 128], Agi[32 * 128], Br[32 * 32], Bi[32 * 32];
    int nx0 = blockIdx.x * 128, ky = blockIdx.y, b = blockIdx.z;
    int tid = threadIdx.x;
    int dg = tid & 7, ng = tid >> 3;

    float acc[8][4] = {};
    for (int c = 0; c < 2; ++c) {
#pragma unroll
        for (int t = 0; t < 8; ++t) {
            int flat = tid + 128 * t;
            int row = flat >> 5, q = flat & 31;
            ((float4*)Agr)[flat] = *(const float4*)(g_Gr + (c * 32 + row) * 512 + nx0 + 4 * q);
            ((float4*)Agi)[flat] = *(const float4*)(g_Gi + (c * 32 + row) * 512 + nx0 + 4 * q);
        }
        const float4* sbr = (const float4*)(g_S3r + (((size_t)b * KYY + ky) * KXX + c * 32) * DVV);
        const float4* sbi = (const float4*)(g_S3i + (((size_t)b * KYY + ky) * KXX + c * 32) * DVV);
#pragma unroll
        for (int t = 0; t < 2; ++t) {
            ((float4*)Br)[tid + 128 * t] = sbr[tid + 128 * t];
            ((float4*)Bi)[tid + 128 * t] = sbi[tid + 128 * t];
        }
        __syncthreads();
#pragma unroll 4
        for (int kk = 0; kk < 32; ++kk) {
            float4 g0 = *(const float4*)(Agr + kk * 128 + 8 * ng);
            float4 g1 = *(const float4*)(Agr + kk * 128 + 8 * ng + 4);
            float4 h0 = *(const float4*)(Agi + kk * 128 + 8 * ng);
            float4 h1 = *(const float4*)(Agi + kk * 128 + 8 * ng + 4);
            float4 br = *(const float4*)(Br + kk * 32 + 4 * dg);
            float4 bi = *(const float4*)(Bi + kk * 32 + 4 * dg);
            float gg[8] = {g0.x, g0.y, g0.z, g0.w, g1.x, g1.y, g1.z, g1.w};
            float hh[8] = {h0.x, h0.y, h0.z, h0.w, h1.x, h1.y, h1.z, h1.w};
            float brr[4] = {br.x, br.y, br.z, br.w};
            float bii[4] = {bi.x, bi.y, bi.z, bi.w};
#pragma unroll
            for (int r = 0; r < 8; ++r)
#pragma unroll
                for (int q = 0; q < 4; ++q) {
                    acc[r][q] = fmaf(gg[r], brr[q], acc[r][q]);
                    acc[r][q] = fmaf(hh[r], bii[q], acc[r][q]);
                }
        }
        __syncthreads();
    }
#pragma unroll
    for (int r = 0; r < 8; ++r) {
        size_t dst = (((size_t)(b * NXX + nx0 + 8 * ng + r)) * KYY + ky) * DVV + 4 * dg;
        *(float4*)(g_S4 + dst) = make_float4(acc[r][0], acc[r][1], acc[r][2], acc[r][3]);
    }
}

// ---------------------------------------------------------------------------
// Step 5 (HMMA): per (b, nx-quad): D[m=(a,dv)=128][n=ny], K=ky=64.
// smem: AH@0 AL@16K BH@32K BL@40K  (48KB)
// ---------------------------------------------------------------------------
__global__ __launch_bounds__(128) void k_step5_mma(float* __restrict__ out) {
    extern __shared__ char smem[];
    u32 sb = smem_u32(smem);
    const u32 sAH = sb, sAL = sb + 16384, sBH = sb + 32768, sBL = sb + 40960;
    int tid = threadIdx.x, w = tid >> 5, lane = tid & 31;
    int nx0 = blockIdx.x * 4, b = blockIdx.y;

    {
        int mrow = w * 32 + lane;
        const float* s4row = g_S4 + ((size_t)(b * 512 + nx0 + w)) * 64 * 32 + lane;
#pragma unroll 8
        for (int k2 = 0; k2 < 32; ++k2) {
            float v0 = s4row[(2 * k2) * 32];
            float v1 = s4row[(2 * k2 + 1) * 32];
            u32 hp, lp;
            split_pair(v0, v1, hp, lp);
            u32 off = SW128((u32)(mrow * 128 + k2 * 4));
            *(u32*)(smem + off) = hp;
            *(u32*)(smem + 16384 + off) = lp;
        }
    }
    __syncthreads();

    u32 ah[2][4][4], al[2][4][4];
#pragma unroll
    for (int mt = 0; mt < 2; ++mt)
#pragma unroll
        for (int kk = 0; kk < 4; ++kk) {
            u32 row = w * 32 + mt * 16 + (lane & 15);
            u32 blk = kk * 2 + (lane >> 4);
            u32 off = SW128(row * 128 + blk * 16);
            ldsm_x4(ah[mt][kk], sAH + off);
            ldsm_x4(al[mt][kk], sAL + off);
        }

    int g = lane >> 2, t4 = lane & 3;
    float* obase = out + ((size_t)(b * 512 + nx0 + w)) * 512 * 32;

    for (int p = 0; p < 8; ++p) {
        __syncthreads();
        {
            const float4* sh = (const float4*)(g_Bth + p * 8192);
            const float4* sl = (const float4*)(g_Btl + p * 8192);
            float4* dh = (float4*)(smem + 32768);
            float4* dl = (float4*)(smem + 40960);
#pragma unroll
            for (int t = 0; t < 4; ++t) { dh[tid + 128 * t] = sh[tid + 128 * t]; dl[tid + 128 * t] = sl[tid + 128 * t]; }
        }
        __syncthreads();

#pragma unroll
        for (int nt = 0; nt < 8; ++nt) {
            u32 bh[4][2], bl[4][2];
#pragma unroll
            for (int kk = 0; kk < 4; ++kk) {
                u32 row = nt * 8 + (lane & 7);
                u32 blk = kk * 2 + ((lane >> 3) & 1);
                u32 off = SW128(row * 128 + blk * 16);
                ldsm_x2(bh[kk], sBH + off);
                ldsm_x2(bl[kk], sBL + off);
            }
            float acc[2][4] = {};
#pragma unroll
            for (int kk = 0; kk < 4; ++kk)
#pragma unroll
                for (int mt = 0; mt < 2; ++mt) {
                    mma_bf16(acc[mt], ah[mt][kk], bh[kk]);
                    mma_bf16(acc[mt], al[mt][kk], bh[kk]);
                    mma_bf16(acc[mt], ah[mt][kk], bl[kk]);
                }
#pragma unroll
            for (int mt = 0; mt < 2; ++mt) {
                int dv1 = mt * 16 + g, dv2 = dv1 + 8;
                int ny0 = p * 64 + nt * 8 + 2 * t4;
                obase[(size_t)ny0 * 32 + dv1]       = acc[mt][0];
                obase[(size_t)(ny0 + 1) * 32 + dv1] = acc[mt][1];
                obase[(size_t)ny0 * 32 + dv2]       = acc[mt][2];
                obase[(size_t)(ny0 + 1) * 32 + dv2] = acc[mt][3];
            }
        }
    }
}

// ---------------------------------------------------------------------------
extern "C" void kernel_launch(void* const* d_in, const int* in_sizes, int n_in,
                              void* d_out, int out_size) {
    const float* x  = (const float*)d_in[0];
    const float* Rr = (const float*)d_in[1];
    const float* Ri = (const float*)d_in[2];
    float* out = (float*)d_out;

    k_precompute<<<128, 256>>>();
    k_step1_mma<<<dim3(128, BB), 128, 49152>>>(x);
    k_step2<<<dim3(KYY, BB), 128>>>();
    k_step3<<<dim3(KXX, KYY / 16, 8), 256>>>(Rr, Ri);
    k_step4<<<dim3(NXX / 128, KYY, BB), 128>>>();
    k_step5_mma<<<dim3(128, BB), 128, 49152>>>(out);
}

// round 8
// speedup vs baseline: 1.5355x; 1.1597x over previous
#include <cuda_runtime.h>
#include <cuda_bf16.h>
#include <math.h>
#include <stdint.h>

typedef unsigned long long u64;
typedef unsigned int u32;

#define BB  4
#define NXX 512
#define NYY 512
#define DVV 32
#define KXX 64
#define KYY 64
#define PI_F 3.14159265358979323846f

#define SW128(o) ((o) ^ (((o) >> 3) & 0x70))

__device__ __forceinline__ u32 smem_u32(const void* p) {
    u32 a;
    asm("{ .reg .u64 t; cvta.to.shared.u64 t, %1; cvt.u32.u64 %0, t; }" : "=r"(a) : "l"(p));
    return a;
}
__device__ __forceinline__ void ldsm_x4(u32* r, u32 addr) {
    asm volatile("ldmatrix.sync.aligned.m8n8.x4.shared.b16 {%0,%1,%2,%3}, [%4];"
                 : "=r"(r[0]), "=r"(r[1]), "=r"(r[2]), "=r"(r[3]) : "r"(addr));
}
__device__ __forceinline__ void ldsm_x2(u32* r, u32 addr) {
    asm volatile("ldmatrix.sync.aligned.m8n8.x2.shared.b16 {%0,%1}, [%2];"
                 : "=r"(r[0]), "=r"(r[1]) : "r"(addr));
}
__device__ __forceinline__ void mma_bf16(float* d, const u32* a, const u32* b) {
    asm volatile("mma.sync.aligned.m16n8k16.row.col.f32.bf16.bf16.f32 "
                 "{%0,%1,%2,%3}, {%4,%5,%6,%7}, {%8,%9}, {%0,%1,%2,%3};"
                 : "+f"(d[0]), "+f"(d[1]), "+f"(d[2]), "+f"(d[3])
                 : "r"(a[0]), "r"(a[1]), "r"(a[2]), "r"(a[3]), "r"(b[0]), "r"(b[1]));
}
__device__ __forceinline__ void split_bf16(float v, __nv_bfloat16 &h, __nv_bfloat16 &l) {
    h = __float2bfloat16(v);
    l = __float2bfloat16(v - __bfloat162float(h));
}
// Fast truncation split of a pair: hp via PRMT, lp = rn(v - trunc(v)) packed.
__device__ __forceinline__ void split_pair(float v0, float v1, u32 &hp, u32 &lp) {
    u32 u0 = __float_as_uint(v0), u1 = __float_as_uint(v1);
    hp = __byte_perm(u0, u1, 0x7632);
    float l0 = v0 - __uint_as_float(u0 & 0xFFFF0000u);
    float l1 = v1 - __uint_as_float(u1 & 0xFFFF0000u);
    asm("cvt.rn.bf16x2.f32 %0, %1, %2;" : "=r"(lp) : "f"(l1), "f"(l0));
}

// bf16 hi/lo B operands as smem tile images (SW128 rows)
// step1: 8 chunks of [64 rows ky][64 k=ny] (8KB each)
__device__ __align__(16) char g_B1h[KYY*NYY*2];
__device__ __align__(16) char g_B1l[KYY*NYY*2];
// step5: 8 passes of [64 rows ny][64 k=ky] (8KB each)
__device__ __align__(16) char g_Bth[NYY*KYY*2];
__device__ __align__(16) char g_Btl[NYY*KYY*2];
// step2: 8 chunks of [128 rows (kx real 0..63 | imag 64..127)][64 k=nx] (16KB each)
__device__ __align__(16) char g_B2h[2*KXX*NXX*2];
__device__ __align__(16) char g_B2l[2*KXX*NXX*2];
// step4: 8 passes of [64 rows nx][64 k=kx] (8KB each), real and imag
__device__ __align__(16) char g_B4rh[NXX*KXX*2];
__device__ __align__(16) char g_B4rl[NXX*KXX*2];
__device__ __align__(16) char g_B4ih[NXX*KXX*2];
__device__ __align__(16) char g_B4il[NXX*KXX*2];

// Scratch
__device__ __align__(16) float g_S1 [(size_t)BB*NXX*KYY*DVV];  // [b][nx][ky][dv]
__device__ __align__(16) float g_S2r[(size_t)BB*KXX*KYY*DVV];  // [b][kx][ky][dv]
__device__ __align__(16) float g_S2i[(size_t)BB*KXX*KYY*DVV];
__device__ __align__(16) float g_S3r[(size_t)BB*KYY*KXX*DVV];  // [b][ky][kx][dv]
__device__ __align__(16) float g_S3i[(size_t)BB*KYY*KXX*DVV];
__device__ __align__(16) float g_S4 [(size_t)BB*NXX*KYY*DVV];  // [b][nx][ky][dv]

// ---------------------------------------------------------------------------
__global__ void k_precompute() {
    int idx = blockIdx.x * blockDim.x + threadIdx.x;
    if (idx >= KXX * NXX) return;
    int k = idx >> 9;          // 0..63
    int n = idx & 511;         // 0..511

    // DCT-II ortho C[k][n]
    float sk = (k == 0) ? sqrtf(1.0f / 512.0f) : sqrtf(2.0f / 512.0f);
    int m = (k * (2 * n + 1)) & 2047;
    float mm1 = (float)((m > 1024) ? (2048 - m) : m);
    float Ckn = sk * cosf(PI_F * mm1 / 1024.0f);
    {
        __nv_bfloat16 h, l;
        split_bf16(Ckn, h, l);
        u32 byte1 = (u32)(n >> 6) * 8192 + SW128((u32)(k * 128 + (n & 63) * 2));
        *(__nv_bfloat16*)(g_B1h + byte1) = h;
        *(__nv_bfloat16*)(g_B1l + byte1) = l;
        u32 byte5 = SW128((u32)(n * 128 + k * 2));
        *(__nv_bfloat16*)(g_Bth + byte5) = h;
        *(__nv_bfloat16*)(g_Btl + byte5) = l;
    }

    // rfft: F[k][n] = (cos, -sin)/sqrt(512)
    int mm = (k * n) & 511;
    float ang = 2.0f * PI_F * (float)mm / 512.0f;
    float isq = sqrtf(1.0f / 512.0f);
    float s, c;
    sincosf(ang, &s, &c);
    float fr = c * isq;
    float fi = -s * isq;
    float ck = (k == 0) ? 1.0f : 2.0f;

    // step2 B images
    {
        __nv_bfloat16 h, l;
        u32 cb = (u32)(n >> 6) * 16384;
        split_bf16(fr, h, l);
        u32 br = cb + SW128((u32)(k * 128 + (n & 63) * 2));
        *(__nv_bfloat16*)(g_B2h + br) = h;
        *(__nv_bfloat16*)(g_B2l + br) = l;
        split_bf16(fi, h, l);
        u32 bi = cb + SW128((u32)((64 + k) * 128 + (n & 63) * 2));
        *(__nv_bfloat16*)(g_B2h + bi) = h;
        *(__nv_bfloat16*)(g_B2l + bi) = l;
    }
    // step4 B images
    {
        __nv_bfloat16 h, l;
        u32 byte = (u32)(n >> 6) * 8192 + SW128((u32)((n & 63) * 128 + k * 2));
        split_bf16(ck * fr, h, l);
        *(__nv_bfloat16*)(g_B4rh + byte) = h;
        *(__nv_bfloat16*)(g_B4rl + byte) = l;
        split_bf16(ck * fi, h, l);
        *(__nv_bfloat16*)(g_B4ih + byte) = h;
        *(__nv_bfloat16*)(g_B4il + byte) = l;
    }
}

// ---------------------------------------------------------------------------
// Step 1 (HMMA): per (b, nx-quad): D[m=(a,dv)=128][n=ky=64] = sum_ny A·B^T
// ---------------------------------------------------------------------------
__global__ __launch_bounds__(128) void k_step1_mma(const float* __restrict__ x) {
    extern __shared__ char smem[];
    u32 sb = smem_u32(smem);
    const u32 sAH = sb, sAL = sb + 16384, sBH = sb + 32768, sBL = sb + 40960;
    int tid = threadIdx.x, w = tid >> 5, lane = tid & 31;
    int nx0 = blockIdx.x * 4, b = blockIdx.y;

    const float* xrow = x + ((size_t)(b * 512 + nx0 + w)) * 512 * 32 + lane;
    int mrow = w * 32 + lane;

    float acc[2][8][4] = {};

    for (int c = 0; c < 8; ++c) {
        {
            const float4* sh = (const float4*)(g_B1h + c * 8192);
            const float4* sl = (const float4*)(g_B1l + c * 8192);
            float4* dh = (float4*)(smem + 32768);
            float4* dl = (float4*)(smem + 40960);
#pragma unroll
            for (int t = 0; t < 4; ++t) { dh[tid + 128 * t] = sh[tid + 128 * t]; dl[tid + 128 * t] = sl[tid + 128 * t]; }
        }
        {
            const float* xc = xrow + (size_t)c * 64 * 32;
#pragma unroll 8
            for (int j2 = 0; j2 < 32; ++j2) {
                float v0 = xc[(2 * j2) * 32];
                float v1 = xc[(2 * j2 + 1) * 32];
                u32 hp, lp;
                split_pair(v0, v1, hp, lp);
                u32 off = SW128((u32)(mrow * 128 + j2 * 4));
                *(u32*)(smem + off) = hp;
                *(u32*)(smem + 16384 + off) = lp;
            }
        }
        __syncthreads();

#pragma unroll
        for (int kk = 0; kk < 4; ++kk) {
            u32 ah[2][4], al[2][4], bh[8][2], bl[8][2];
#pragma unroll
            for (int mt = 0; mt < 2; ++mt) {
                u32 row = w * 32 + mt * 16 + (lane & 15);
                u32 blk = kk * 2 + (lane >> 4);
                u32 off = SW128(row * 128 + blk * 16);
                ldsm_x4(ah[mt], sAH + off);
                ldsm_x4(al[mt], sAL + off);
            }
#pragma unroll
            for (int nt = 0; nt < 8; ++nt) {
                u32 row = nt * 8 + (lane & 7);
                u32 blk = kk * 2 + ((lane >> 3) & 1);
                u32 off = SW128(row * 128 + blk * 16);
                ldsm_x2(bh[nt], sBH + off);
                ldsm_x2(bl[nt], sBL + off);
            }
#pragma unroll
            for (int mt = 0; mt < 2; ++mt)
#pragma unroll
                for (int nt = 0; nt < 8; ++nt) {
                    mma_bf16(acc[mt][nt], ah[mt], bh[nt]);
                    mma_bf16(acc[mt][nt], al[mt], bh[nt]);
                    mma_bf16(acc[mt][nt], ah[mt], bl[nt]);
                }
        }
        __syncthreads();
    }

    int g = lane >> 2, t4 = lane & 3;
    float* obase = g_S1 + ((size_t)(b * 512 + nx0 + w)) * 64 * 32;
#pragma unroll
    for (int mt = 0; mt < 2; ++mt)
#pragma unroll
        for (int nt = 0; nt < 8; ++nt) {
            int dv1 = mt * 16 + g, dv2 = dv1 + 8;
            int ky0 = nt * 8 + 2 * t4;
            obase[ky0 * 32 + dv1]       = acc[mt][nt][0];
            obase[(ky0 + 1) * 32 + dv1] = acc[mt][nt][1];
            obase[ky0 * 32 + dv2]       = acc[mt][nt][2];
            obase[(ky0 + 1) * 32 + dv2] = acc[mt][nt][3];
        }
}

// ---------------------------------------------------------------------------
// Step 2 (HMMA, high-occupancy): per (b, ky): D[m=dv=32][n=kx r|i=128]
//  = sum_nx A[dv][nx]·B[n][nx]. K=512 in 8 chunks.
// smem: AH@0(4K) AL@4K BH@8K(16K) BL@24K  = 40KB
// ---------------------------------------------------------------------------
__global__ __launch_bounds__(128) void k_step2n() {
    extern __shared__ char smem[];
    u32 sb = smem_u32(smem);
    const u32 sAH = sb, sAL = sb + 4096, sBH = sb + 8192, sBL = sb + 24576;
    int tid = threadIdx.x, w = tid >> 5, lane = tid & 31;
    int ky = blockIdx.x, b = blockIdx.y;
    int dv = tid & 31, jg = tid >> 5;
    const float* s1 = g_S1 + (size_t)b * 512 * 2048 + (size_t)ky * 32 + dv;

    float acc[2][4][4] = {};   // [mt][nt_local]

    for (int c = 0; c < 8; ++c) {
        // stage B chunk image (16KB hi + 16KB lo)
        {
            const float4* sh = (const float4*)(g_B2h + c * 16384);
            const float4* sl = (const float4*)(g_B2l + c * 16384);
            float4* dh = (float4*)(smem + 8192);
            float4* dl = (float4*)(smem + 24576);
#pragma unroll
            for (int t = 0; t < 8; ++t) { dh[tid + 128 * t] = sh[tid + 128 * t]; dl[tid + 128 * t] = sl[tid + 128 * t]; }
        }
        // stage A [32 rows dv][64 nx] hi/lo
        {
            const float* src = s1 + (size_t)(c * 64) * 2048;
#pragma unroll
            for (int it = 0; it < 8; ++it) {
                int j = jg + 4 * it;
                float v0 = src[(2 * j) * 2048];
                float v1 = src[(2 * j + 1) * 2048];
                u32 hp, lp;
                split_pair(v0, v1, hp, lp);
                u32 off = SW128((u32)(dv * 128 + j * 4));
                *(u32*)(smem + off) = hp;
                *(u32*)(smem + 4096 + off) = lp;
            }
        }
        __syncthreads();

#pragma unroll
        for (int kk = 0; kk < 4; ++kk) {
            u32 ah[2][4], al[2][4];
#pragma unroll
            for (int mt = 0; mt < 2; ++mt) {
                u32 row = mt * 16 + (lane & 15);
                u32 blk = kk * 2 + (lane >> 4);
                u32 off = SW128(row * 128 + blk * 16);
                ldsm_x4(ah[mt], sAH + off);
                ldsm_x4(al[mt], sAL + off);
            }
#pragma unroll
            for (int nt = 0; nt < 4; ++nt) {
                u32 row = (w * 4 + nt) * 8 + (lane & 7);
                u32 blk = kk * 2 + ((lane >> 3) & 1);
                u32 off = SW128(row * 128 + blk * 16);
                u32 bh[2], bl[2];
                ldsm_x2(bh, sBH + off);
                ldsm_x2(bl, sBL + off);
#pragma unroll
                for (int mt = 0; mt < 2; ++mt) {
                    mma_bf16(acc[mt][nt], ah[mt], bh);
                    mma_bf16(acc[mt][nt], al[mt], bh);
                    mma_bf16(acc[mt][nt], ah[mt], bl);
                }
            }
        }
        __syncthreads();
    }

    int g = lane >> 2, t4 = lane & 3;
#pragma unroll
    for (int nt = 0; nt < 4; ++nt) {
        int col = (w * 4 + nt) * 8 + 2 * t4;        // 0..127
        int imag = col >> 6;
        int kx = col & 63;
        float* dst = imag ? g_S2i : g_S2r;
        size_t base = ((size_t)(b * 64 + kx) * 64 + ky) * 32;
#pragma unroll
        for (int mt = 0; mt < 2; ++mt) {
            int dv1 = mt * 16 + g, dv2 = dv1 + 8;
            dst[base + dv1]            = acc[mt][nt][0];
            dst[base + 2048 + dv1]     = acc[mt][nt][1];
            dst[base + dv2]            = acc[mt][nt][2];
            dst[base + 2048 + dv2]     = acc[mt][nt][3];
        }
    }
}

// ---------------------------------------------------------------------------
// Step 3: per-mode complex channel mix, ic split on blockIdx.z
// ---------------------------------------------------------------------------
__global__ __launch_bounds__(256) void k_step3(const float* __restrict__ Rr,
                                               const float* __restrict__ Ri) {
    __shared__ float Xr[4 * 16 * 33], Xi[4 * 16 * 33];
    __shared__ float Sr[4 * 32 * 16], Si[4 * 32 * 16];
    __shared__ float Yr[64 * 4], Yi[64 * 4];
    int kx = blockIdx.x, ky0 = blockIdx.y * 16, ic = blockIdx.z;
    int tid = threadIdx.x;
    int lane = tid & 31, w = tid >> 5;

#pragma unroll
    for (int r = 0; r < 8; ++r) {
        int row = w * 8 + r;
        int e = row >> 4, u = row & 15;
        size_t src = (((size_t)e * KXX + kx) * KYY + ky0 + u) * DVV + lane;
        Xr[(e * 16 + u) * 33 + lane] = g_S2r[src];
        Xi[(e * 16 + u) * 33 + lane] = g_S2i[src];
    }
#pragma unroll
    for (int t = 0; t < 8; ++t) {
        int flat = tid + 256 * t;
        int row = flat >> 4, uu = flat & 15;
        int i4 = row >> 5, j = row & 31;
        size_t src = (((size_t)(ic * 4 + i4) * DVV + j) * KXX + kx) * KYY + ky0 + uu;
        Sr[(i4 * 32 + j) * 16 + uu] = Rr[src];
        Si[(i4 * 32 + j) * 16 + uu] = Ri[src];
    }
    __syncthreads();

    int u = tid & 15, e = (tid >> 4) & 3, ii = tid >> 6;
    float ar = 0.f, ai = 0.f;
#pragma unroll 8
    for (int j = 0; j < 32; ++j) {
        float xr = Xr[(e * 16 + u) * 33 + j];
        float xi = Xi[(e * 16 + u) * 33 + j];
        float rr = Sr[(ii * 32 + j) * 16 + u];
        float ri = Si[(ii * 32 + j) * 16 + u];
        ar = fmaf(rr, xr, ar);
        ar = fmaf(-ri, xi, ar);
        ai = fmaf(rr, xi, ai);
        ai = fmaf(ri, xr, ai);
    }
    Yr[(e * 16 + u) * 4 + ii] = ar;
    Yi[(e * 16 + u) * 4 + ii] = ai;
    __syncthreads();

    if (tid < 128) {
        int row = tid & 63, which = tid >> 6;
        int ee = row >> 4, uu = row & 15;
        float4 v = ((const float4*)(which ? Yi : Yr))[row];
        size_t dst = (((size_t)ee * KYY + ky0 + uu) * KXX + kx) * DVV + ic * 4;
        *(float4*)((which ? g_S3i : g_S3r) + dst) = v;
    }
}

// ---------------------------------------------------------------------------
// Step 4 (HMMA, high-occupancy): per (b, ky): D[m=dv=32][n=nx, 8 passes of 64]
//  = sum_kx Ar·Br + Ai·Bi.
// smem: ArH@0 ArL@4K AiH@8K AiL@12K | BrH@16K BrL@24K BiH@32K BiL@40K = 48KB
// ---------------------------------------------------------------------------
__global__ __launch_bounds__(128) void k_step4n() {
    extern __shared__ char smem[];
    u32 sb = smem_u32(smem);
    const u32 sA[2][2] = {{sb, sb + 4096}, {sb + 8192, sb + 12288}};       // [ri][hl]
    const u32 sB[2][2] = {{sb + 16384, sb + 24576}, {sb + 32768, sb + 40960}};
    int tid = threadIdx.x, w = tid >> 5, lane = tid & 31;
    int ky = blockIdx.x, b = blockIdx.y;
    int dv = tid & 31, jg = tid >> 5;

    // stage A once: [32 rows dv][64 kx] hi/lo for real and imag
    {
        size_t base = ((size_t)(b * 64 + ky) * 64) * 32 + dv;
        const float* s3r = g_S3r + base;
        const float* s3i = g_S3i + base;
#pragma unroll
        for (int it = 0; it < 8; ++it) {
            int j = jg + 4 * it;            // kx pair 0..31
            u32 off = SW128((u32)(dv * 128 + j * 4));
            u32 hp, lp;
            split_pair(s3r[(2 * j) * 32], s3r[(2 * j + 1) * 32], hp, lp);
            *(u32*)(smem + off) = hp;
            *(u32*)(smem + 4096 + off) = lp;
            split_pair(s3i[(2 * j) * 32], s3i[(2 * j + 1) * 32], hp, lp);
            *(u32*)(smem + 8192 + off) = hp;
            *(u32*)(smem + 12288 + off) = lp;
        }
    }

    int g = lane >> 2, t4 = lane & 3;

    for (int p = 0; p < 8; ++p) {
        // stage B pass (r and i images, 8KB each × hi/lo)
        {
            const float4* s0 = (const float4*)(g_B4rh + p * 8192);
            const float4* s1p = (const float4*)(g_B4rl + p * 8192);
            const float4* s2p = (const float4*)(g_B4ih + p * 8192);
            const float4* s3p = (const float4*)(g_B4il + p * 8192);
#pragma unroll
            for (int t = 0; t < 4; ++t) {
                ((float4*)(smem + 16384))[tid + 128 * t] = s0[tid + 128 * t];
                ((float4*)(smem + 24576))[tid + 128 * t] = s1p[tid + 128 * t];
                ((float4*)(smem + 32768))[tid + 128 * t] = s2p[tid + 128 * t];
                ((float4*)(smem + 40960))[tid + 128 * t] = s3p[tid + 128 * t];
            }
        }
        __syncthreads();

        float acc[2][2][4] = {};    // [mt][nt_local]
#pragma unroll
        for (int ri = 0; ri < 2; ++ri) {
#pragma unroll
            for (int kk = 0; kk < 4; ++kk) {
                u32 ah[2][4], al[2][4];
#pragma unroll
                for (int mt = 0; mt < 2; ++mt) {
                    u32 row = mt * 16 + (lane & 15);
                    u32 blk = kk * 2 + (lane >> 4);
                    u32 off = SW128(row * 128 + blk * 16);
                    ldsm_x4(ah[mt], sA[ri][0] + off);
                    ldsm_x4(al[mt], sA[ri][1] + off);
                }
#pragma unroll
                for (int nt = 0; nt < 2; ++nt) {
                    u32 row = (w * 2 + nt) * 8 + (lane & 7);
                    u32 blk = kk * 2 + ((lane >> 3) & 1);
                    u32 off = SW128(row * 128 + blk * 16);
                    u32 bh[2], bl[2];
                    ldsm_x2(bh, sB[ri][0] + off);
                    ldsm_x2(bl, sB[ri][1] + off);
#pragma unroll
                    for (int mt = 0; mt < 2; ++mt) {
                        mma_bf16(acc[mt][nt], ah[mt], bh);
                        mma_bf16(acc[mt][nt], al[mt], bh);
                        mma_bf16(acc[mt][nt], ah[mt], bl);
                    }
                }
            }
        }
        // store pass results
#pragma unroll
        for (int nt = 0; nt < 2; ++nt) {
            int nx = p * 64 + (w * 2 + nt) * 8 + 2 * t4;
            size_t base = ((size_t)(b * 512 + nx) * 64 + ky) * 32;
#pragma unroll
            for (int mt = 0; mt < 2; ++mt) {
                int dv1 = mt * 16 + g, dv2 = dv1 + 8;
                g_S4[base + dv1]        = acc[mt][nt][0];
                g_S4[base + 2048 + dv1] = acc[mt][nt][1];
                g_S4[base + dv2]        = acc[mt][nt][2];
                g_S4[base + 2048 + dv2] = acc[mt][nt][3];
            }
        }
        __syncthreads();
    }
}

// ---------------------------------------------------------------------------
// Step 5 (HMMA): per (b, nx-quad): D[m=(a,dv)=128][n=ny], K=ky=64.
// ---------------------------------------------------------------------------
__global__ __launch_bounds__(128) void k_step5_mma(float* __restrict__ out) {
    extern __shared__ char smem[];
    u32 sb = smem_u32(smem);
    const u32 sAH = sb, sAL = sb + 16384, sBH = sb + 32768, sBL = sb + 40960;
    int tid = threadIdx.x, w = tid >> 5, lane = tid & 31;
    int nx0 = blockIdx.x * 4, b = blockIdx.y;

    {
        int mrow = w * 32 + lane;
        const float* s4row = g_S4 + ((size_t)(b * 512 + nx0 + w)) * 64 * 32 + lane;
#pragma unroll 8
        for (int k2 = 0; k2 < 32; ++k2) {
            float v0 = s4row[(2 * k2) * 32];
            float v1 = s4row[(2 * k2 + 1) * 32];
            u32 hp, lp;
            split_pair(v0, v1, hp, lp);
            u32 off = SW128((u32)(mrow * 128 + k2 * 4));
            *(u32*)(smem + off) = hp;
            *(u32*)(smem + 16384 + off) = lp;
        }
    }
    __syncthreads();

    u32 ah[2][4][4], al[2][4][4];
#pragma unroll
    for (int mt = 0; mt < 2; ++mt)
#pragma unroll
        for (int kk = 0; kk < 4; ++kk) {
            u32 row = w * 32 + mt * 16 + (lane & 15);
            u32 blk = kk * 2 + (lane >> 4);
            u32 off = SW128(row * 128 + blk * 16);
            ldsm_x4(ah[mt][kk], sAH + off);
            ldsm_x4(al[mt][kk], sAL + off);
        }

    int g = lane >> 2, t4 = lane & 3;
    float* obase = out + ((size_t)(b * 512 + nx0 + w)) * 512 * 32;

    for (int p = 0; p < 8; ++p) {
        __syncthreads();
        {
            const float4* sh = (const float4*)(g_Bth + p * 8192);
            const float4* sl = (const float4*)(g_Btl + p * 8192);
            float4* dh = (float4*)(smem + 32768);
            float4* dl = (float4*)(smem + 40960);
#pragma unroll
            for (int t = 0; t < 4; ++t) { dh[tid + 128 * t] = sh[tid + 128 * t]; dl[tid + 128 * t] = sl[tid + 128 * t]; }
        }
        __syncthreads();

#pragma unroll
        for (int nt = 0; nt < 8; ++nt) {
            u32 bh[4][2], bl[4][2];
#pragma unroll
            for (int kk = 0; kk < 4; ++kk) {
                u32 row = nt * 8 + (lane & 7);
                u32 blk = kk * 2 + ((lane >> 3) & 1);
                u32 off = SW128(row * 128 + blk * 16);
                ldsm_x2(bh[kk], sBH + off);
                ldsm_x2(bl[kk], sBL + off);
            }
            float acc[2][4] = {};
#pragma unroll
            for (int kk = 0; kk < 4; ++kk)
#pragma unroll
                for (int mt = 0; mt < 2; ++mt) {
                    mma_bf16(acc[mt], ah[mt][kk], bh[kk]);
                    mma_bf16(acc[mt], al[mt][kk], bh[kk]);
                    mma_bf16(acc[mt], ah[mt][kk], bl[kk]);
                }
#pragma unroll
            for (int mt = 0; mt < 2; ++mt) {
                int dv1 = mt * 16 + g, dv2 = dv1 + 8;
                int ny0 = p * 64 + nt * 8 + 2 * t4;
                obase[(size_t)ny0 * 32 + dv1]       = acc[mt][0];
                obase[(size_t)(ny0 + 1) * 32 + dv1] = acc[mt][1];
                obase[(size_t)ny0 * 32 + dv2]       = acc[mt][2];
                obase[(size_t)(ny0 + 1) * 32 + dv2] = acc[mt][3];
            }
        }
    }
}

// ---------------------------------------------------------------------------
extern "C" void kernel_launch(void* const* d_in, const int* in_sizes, int n_in,
                              void* d_out, int out_size) {
    const float* x  = (const float*)d_in[0];
    const float* Rr = (const float*)d_in[1];
    const float* Ri = (const float*)d_in[2];
    float* out = (float*)d_out;

    k_precompute<<<128, 256>>>();
    k_step1_mma<<<dim3(128, BB), 128, 49152>>>(x);
    k_step2n<<<dim3(64, BB), 128, 40960>>>();
    k_step3<<<dim3(KXX, KYY / 16, 8), 256>>>(Rr, Ri);
    k_step4n<<<dim3(64, BB), 128, 49152>>>();
    k_step5_mma<<<dim3(128, BB), 128, 49152>>>(out);
}

// round 9
// speedup vs baseline: 1.8530x; 1.2068x over previous
#include <cuda_runtime.h>
#include <cuda_fp16.h>
#include <math.h>
#include <stdint.h>

typedef unsigned long long u64;
typedef unsigned int u32;

#define BB  4
#define NXX 512
#define NYY 512
#define DVV 32
#define KXX 64
#define KYY 64
#define PI_F 3.14159265358979323846f

#define SW128(o) ((o) ^ (((o) >> 3) & 0x70))

__device__ __forceinline__ u32 smem_u32(const void* p) {
    u32 a;
    asm("{ .reg .u64 t; cvta.to.shared.u64 t, %1; cvt.u32.u64 %0, t; }" : "=r"(a) : "l"(p));
    return a;
}
__device__ __forceinline__ void ldsm_x4(u32* r, u32 addr) {
    asm volatile("ldmatrix.sync.aligned.m8n8.x4.shared.b16 {%0,%1,%2,%3}, [%4];"
                 : "=r"(r[0]), "=r"(r[1]), "=r"(r[2]), "=r"(r[3]) : "r"(addr));
}
__device__ __forceinline__ void ldsm_x2(u32* r, u32 addr) {
    asm volatile("ldmatrix.sync.aligned.m8n8.x2.shared.b16 {%0,%1}, [%2];"
                 : "=r"(r[0]), "=r"(r[1]) : "r"(addr));
}
__device__ __forceinline__ void mma_f16(float* d, const u32* a, const u32* b) {
    asm volatile("mma.sync.aligned.m16n8k16.row.col.f32.f16.f16.f32 "
                 "{%0,%1,%2,%3}, {%4,%5,%6,%7}, {%8,%9}, {%0,%1,%2,%3};"
                 : "+f"(d[0]), "+f"(d[1]), "+f"(d[2]), "+f"(d[3])
                 : "r"(a[0]), "r"(a[1]), "r"(a[2]), "r"(a[3]), "r"(b[0]), "r"(b[1]));
}
// fp16 hi/lo split of a pair: hp = rn(f16) pair; lp = rn(v - h) pair.
__device__ __forceinline__ void split_pair_f16(float v0, float v1, u32 &hp, u32 &lp) {
    asm("cvt.rn.f16x2.f32 %0, %1, %2;" : "=r"(hp) : "f"(v1), "f"(v0));
    __half2 h2 = *reinterpret_cast<__half2*>(&hp);
    float l0 = v0 - __low2float(h2);
    float l1 = v1 - __high2float(h2);
    asm("cvt.rn.f16x2.f32 %0, %1, %2;" : "=r"(lp) : "f"(l1), "f"(l0));
}

// fp16 B operands as smem tile images (SW128 rows), single rounded plane
// step1: 8 chunks of [64 rows ky][64 k=ny] (8KB each)
__device__ __align__(16) char g_B1h[KYY*NYY*2];
// step5: 8 passes of [64 rows ny][64 k=ky] (8KB each)
__device__ __align__(16) char g_Bth[NYY*KYY*2];
// step2: 8 chunks of [128 rows (kx real | imag)][64 k=nx] (16KB each)
__device__ __align__(16) char g_B2h[2*KXX*NXX*2];
// step4: 8 passes of [64 rows nx][64 k=kx] (8KB each), real and imag
__device__ __align__(16) char g_B4rh[NXX*KXX*2];
__device__ __align__(16) char g_B4ih[NXX*KXX*2];

// Scratch
__device__ __align__(16) float g_S1 [(size_t)BB*NXX*KYY*DVV];  // [b][nx][ky][dv]
__device__ __align__(16) float g_S2r[(size_t)BB*KXX*KYY*DVV];  // [b][kx][ky][dv]
__device__ __align__(16) float g_S2i[(size_t)BB*KXX*KYY*DVV];
__device__ __align__(16) float g_S3r[(size_t)BB*KYY*KXX*DVV];  // [b][ky][kx][dv]
__device__ __align__(16) float g_S3i[(size_t)BB*KYY*KXX*DVV];
__device__ __align__(16) float g_S4 [(size_t)BB*NXX*KYY*DVV];  // [b][nx][ky][dv]

// ---------------------------------------------------------------------------
__global__ void k_precompute() {
    int idx = blockIdx.x * blockDim.x + threadIdx.x;
    if (idx >= KXX * NXX) return;
    int k = idx >> 9;          // 0..63
    int n = idx & 511;         // 0..511

    // DCT-II ortho C[k][n]
    float sk = (k == 0) ? sqrtf(1.0f / 512.0f) : sqrtf(2.0f / 512.0f);
    int m = (k * (2 * n + 1)) & 2047;
    float mm1 = (float)((m > 1024) ? (2048 - m) : m);
    float Ckn = sk * cosf(PI_F * mm1 / 1024.0f);
    {
        __half h = __float2half_rn(Ckn);
        u32 byte1 = (u32)(n >> 6) * 8192 + SW128((u32)(k * 128 + (n & 63) * 2));
        *(__half*)(g_B1h + byte1) = h;
        u32 byte5 = SW128((u32)(n * 128 + k * 2));
        *(__half*)(g_Bth + byte5) = h;
    }

    // rfft: F[k][n] = (cos, -sin)/sqrt(512)
    int mm = (k * n) & 511;
    float ang = 2.0f * PI_F * (float)mm / 512.0f;
    float isq = sqrtf(1.0f / 512.0f);
    float s, c;
    sincosf(ang, &s, &c);
    float fr = c * isq;
    float fi = -s * isq;
    float ck = (k == 0) ? 1.0f : 2.0f;

    // step2 B images
    {
        u32 cb = (u32)(n >> 6) * 16384;
        u32 br = cb + SW128((u32)(k * 128 + (n & 63) * 2));
        *(__half*)(g_B2h + br) = __float2half_rn(fr);
        u32 bi = cb + SW128((u32)((64 + k) * 128 + (n & 63) * 2));
        *(__half*)(g_B2h + bi) = __float2half_rn(fi);
    }
    // step4 B images
    {
        u32 byte = (u32)(n >> 6) * 8192 + SW128((u32)((n & 63) * 128 + k * 2));
        *(__half*)(g_B4rh + byte) = __float2half_rn(ck * fr);
        *(__half*)(g_B4ih + byte) = __float2half_rn(ck * fi);
    }
}

// ---------------------------------------------------------------------------
// Step 1 (HMMA fp16): per (b, nx-quad): D[m=(a,dv)=128][n=ky=64] = sum_ny A·B^T
// smem: AH@0(16K) AL@16K BH@32K(8K) = 40KB
// ---------------------------------------------------------------------------
__global__ __launch_bounds__(128) void k_step1_mma(const float* __restrict__ x) {
    extern __shared__ char smem[];
    u32 sb = smem_u32(smem);
    const u32 sAH = sb, sAL = sb + 16384, sBH = sb + 32768;
    int tid = threadIdx.x, w = tid >> 5, lane = tid & 31;
    int nx0 = blockIdx.x * 4, b = blockIdx.y;

    const float* xrow = x + ((size_t)(b * 512 + nx0 + w)) * 512 * 32 + lane;
    int mrow = w * 32 + lane;

    float acc[2][8][4] = {};

    for (int c = 0; c < 8; ++c) {
        {
            const float4* sh = (const float4*)(g_B1h + c * 8192);
            float4* dh = (float4*)(smem + 32768);
#pragma unroll
            for (int t = 0; t < 4; ++t) dh[tid + 128 * t] = sh[tid + 128 * t];
        }
        {
            const float* xc = xrow + (size_t)c * 64 * 32;
#pragma unroll 8
            for (int j2 = 0; j2 < 32; ++j2) {
                float v0 = xc[(2 * j2) * 32];
                float v1 = xc[(2 * j2 + 1) * 32];
                u32 hp, lp;
                split_pair_f16(v0, v1, hp, lp);
                u32 off = SW128((u32)(mrow * 128 + j2 * 4));
                *(u32*)(smem + off) = hp;
                *(u32*)(smem + 16384 + off) = lp;
            }
        }
        __syncthreads();

#pragma unroll
        for (int kk = 0; kk < 4; ++kk) {
            u32 ah[2][4], al[2][4], bh[8][2];
#pragma unroll
            for (int mt = 0; mt < 2; ++mt) {
                u32 row = w * 32 + mt * 16 + (lane & 15);
                u32 blk = kk * 2 + (lane >> 4);
                u32 off = SW128(row * 128 + blk * 16);
                ldsm_x4(ah[mt], sAH + off);
                ldsm_x4(al[mt], sAL + off);
            }
#pragma unroll
            for (int nt = 0; nt < 8; ++nt) {
                u32 row = nt * 8 + (lane & 7);
                u32 blk = kk * 2 + ((lane >> 3) & 1);
                u32 off = SW128(row * 128 + blk * 16);
                ldsm_x2(bh[nt], sBH + off);
            }
#pragma unroll
            for (int mt = 0; mt < 2; ++mt)
#pragma unroll
                for (int nt = 0; nt < 8; ++nt) {
                    mma_f16(acc[mt][nt], ah[mt], bh[nt]);
                    mma_f16(acc[mt][nt], al[mt], bh[nt]);
                }
        }
        __syncthreads();
    }

    int g = lane >> 2, t4 = lane & 3;
    float* obase = g_S1 + ((size_t)(b * 512 + nx0 + w)) * 64 * 32;
#pragma unroll
    for (int mt = 0; mt < 2; ++mt)
#pragma unroll
        for (int nt = 0; nt < 8; ++nt) {
            int dv1 = mt * 16 + g, dv2 = dv1 + 8;
            int ky0 = nt * 8 + 2 * t4;
            obase[ky0 * 32 + dv1]       = acc[mt][nt][0];
            obase[(ky0 + 1) * 32 + dv1] = acc[mt][nt][1];
            obase[ky0 * 32 + dv2]       = acc[mt][nt][2];
            obase[(ky0 + 1) * 32 + dv2] = acc[mt][nt][3];
        }
}

// ---------------------------------------------------------------------------
// Step 2 (HMMA fp16): per (b, ky): D[m=dv=32][n=kx r|i=128] = sum_nx A·B^T
// smem: AH@0(4K) AL@4K BH@8K(16K) = 24KB
// ---------------------------------------------------------------------------
__global__ __launch_bounds__(128) void k_step2n() {
    extern __shared__ char smem[];
    u32 sb = smem_u32(smem);
    const u32 sAH = sb, sAL = sb + 4096, sBH = sb + 8192;
    int tid = threadIdx.x, w = tid >> 5, lane = tid & 31;
    int ky = blockIdx.x, b = blockIdx.y;
    int dv = tid & 31, jg = tid >> 5;
    const float* s1 = g_S1 + (size_t)b * 512 * 2048 + (size_t)ky * 32 + dv;

    float acc[2][4][4] = {};   // [mt][nt_local]

    for (int c = 0; c < 8; ++c) {
        {
            const float4* sh = (const float4*)(g_B2h + c * 16384);
            float4* dh = (float4*)(smem + 8192);
#pragma unroll
            for (int t = 0; t < 8; ++t) dh[tid + 128 * t] = sh[tid + 128 * t];
        }
        {
            const float* src = s1 + (size_t)(c * 64) * 2048;
#pragma unroll
            for (int it = 0; it < 8; ++it) {
                int j = jg + 4 * it;
                float v0 = src[(2 * j) * 2048];
                float v1 = src[(2 * j + 1) * 2048];
                u32 hp, lp;
                split_pair_f16(v0, v1, hp, lp);
                u32 off = SW128((u32)(dv * 128 + j * 4));
                *(u32*)(smem + off) = hp;
                *(u32*)(smem + 4096 + off) = lp;
            }
        }
        __syncthreads();

#pragma unroll
        for (int kk = 0; kk < 4; ++kk) {
            u32 ah[2][4], al[2][4];
#pragma unroll
            for (int mt = 0; mt < 2; ++mt) {
                u32 row = mt * 16 + (lane & 15);
                u32 blk = kk * 2 + (lane >> 4);
                u32 off = SW128(row * 128 + blk * 16);
                ldsm_x4(ah[mt], sAH + off);
                ldsm_x4(al[mt], sAL + off);
            }
#pragma unroll
            for (int nt = 0; nt < 4; ++nt) {
                u32 row = (w * 4 + nt) * 8 + (lane & 7);
                u32 blk = kk * 2 + ((lane >> 3) & 1);
                u32 off = SW128(row * 128 + blk * 16);
                u32 bh[2];
                ldsm_x2(bh, sBH + off);
#pragma unroll
                for (int mt = 0; mt < 2; ++mt) {
                    mma_f16(acc[mt][nt], ah[mt], bh);
                    mma_f16(acc[mt][nt], al[mt], bh);
                }
            }
        }
        __syncthreads();
    }

    int g = lane >> 2, t4 = lane & 3;
#pragma unroll
    for (int nt = 0; nt < 4; ++nt) {
        int col = (w * 4 + nt) * 8 + 2 * t4;        // 0..127
        int imag = col >> 6;
        int kx = col & 63;
        float* dst = imag ? g_S2i : g_S2r;
        size_t base = ((size_t)(b * 64 + kx) * 64 + ky) * 32;
#pragma unroll
        for (int mt = 0; mt < 2; ++mt) {
            int dv1 = mt * 16 + g, dv2 = dv1 + 8;
            dst[base + dv1]            = acc[mt][nt][0];
            dst[base + 2048 + dv1]     = acc[mt][nt][1];
            dst[base + dv2]            = acc[mt][nt][2];
            dst[base + 2048 + dv2]     = acc[mt][nt][3];
        }
    }
}

// ---------------------------------------------------------------------------
// Step 3: per-mode complex channel mix, ic split on blockIdx.z
// ---------------------------------------------------------------------------
__global__ __launch_bounds__(256) void k_step3(const float* __restrict__ Rr,
                                               const float* __restrict__ Ri) {
    __shared__ float Xr[4 * 16 * 33], Xi[4 * 16 * 33];
    __shared__ float Sr[4 * 32 * 16], Si[4 * 32 * 16];
    __shared__ float Yr[64 * 4], Yi[64 * 4];
    int kx = blockIdx.x, ky0 = blockIdx.y * 16, ic = blockIdx.z;
    int tid = threadIdx.x;
    int lane = tid & 31, w = tid >> 5;

#pragma unroll
    for (int r = 0; r < 8; ++r) {
        int row = w * 8 + r;
        int e = row >> 4, u = row & 15;
        size_t src = (((size_t)e * KXX + kx) * KYY + ky0 + u) * DVV + lane;
        Xr[(e * 16 + u) * 33 + lane] = g_S2r[src];
        Xi[(e * 16 + u) * 33 + lane] = g_S2i[src];
    }
#pragma unroll
    for (int t = 0; t < 8; ++t) {
        int flat = tid + 256 * t;
        int row = flat >> 4, uu = flat & 15;
        int i4 = row >> 5, j = row & 31;
        size_t src = (((size_t)(ic * 4 + i4) * DVV + j) * KXX + kx) * KYY + ky0 + uu;
        Sr[(i4 * 32 + j) * 16 + uu] = Rr[src];
        Si[(i4 * 32 + j) * 16 + uu] = Ri[src];
    }
    __syncthreads();

    int u = tid & 15, e = (tid >> 4) & 3, ii = tid >> 6;
    float ar = 0.f, ai = 0.f;
#pragma unroll 8
    for (int j = 0; j < 32; ++j) {
        float xr = Xr[(e * 16 + u) * 33 + j];
        float xi = Xi[(e * 16 + u) * 33 + j];
        float rr = Sr[(ii * 32 + j) * 16 + u];
        float ri = Si[(ii * 32 + j) * 16 + u];
        ar = fmaf(rr, xr, ar);
        ar = fmaf(-ri, xi, ar);
        ai = fmaf(rr, xi, ai);
        ai = fmaf(ri, xr, ai);
    }
    Yr[(e * 16 + u) * 4 + ii] = ar;
    Yi[(e * 16 + u) * 4 + ii] = ai;
    __syncthreads();

    if (tid < 128) {
        int row = tid & 63, which = tid >> 6;
        int ee = row >> 4, uu = row & 15;
        float4 v = ((const float4*)(which ? Yi : Yr))[row];
        size_t dst = (((size_t)ee * KYY + ky0 + uu) * KXX + kx) * DVV + ic * 4;
        *(float4*)((which ? g_S3i : g_S3r) + dst) = v;
    }
}

// ---------------------------------------------------------------------------
// Step 4 (HMMA fp16): per (b, ky): D[m=dv=32][n=nx, 8 passes of 64]
//  = sum_kx Ar·Br + Ai·Bi.
// smem: ArH@0 ArL@4K AiH@8K AiL@12K | BrH@16K(8K) BiH@24K(8K) = 32KB
// ---------------------------------------------------------------------------
__global__ __launch_bounds__(128) void k_step4n() {
    extern __shared__ char smem[];
    u32 sb = smem_u32(smem);
    const u32 sA[2][2] = {{sb, sb + 4096}, {sb + 8192, sb + 12288}};   // [ri][hl]
    const u32 sB[2] = {sb + 16384, sb + 24576};                        // [ri]
    int tid = threadIdx.x, w = tid >> 5, lane = tid & 31;
    int ky = blockIdx.x, b = blockIdx.y;
    int dv = tid & 31, jg = tid >> 5;

    // stage A once: [32 rows dv][64 kx] hi/lo for real and imag
    {
        size_t base = ((size_t)(b * 64 + ky) * 64) * 32 + dv;
        const float* s3r = g_S3r + base;
        const float* s3i = g_S3i + base;
#pragma unroll
        for (int it = 0; it < 8; ++it) {
            int j = jg + 4 * it;            // kx pair 0..31
            u32 off = SW128((u32)(dv * 128 + j * 4));
            u32 hp, lp;
            split_pair_f16(s3r[(2 * j) * 32], s3r[(2 * j + 1) * 32], hp, lp);
            *(u32*)(smem + off) = hp;
            *(u32*)(smem + 4096 + off) = lp;
            split_pair_f16(s3i[(2 * j) * 32], s3i[(2 * j + 1) * 32], hp, lp);
            *(u32*)(smem + 8192 + off) = hp;
            *(u32*)(smem + 12288 + off) = lp;
        }
    }

    int g = lane >> 2, t4 = lane & 3;

    for (int p = 0; p < 8; ++p) {
        // stage B pass (r and i images)
        {
            const float4* s0 = (const float4*)(g_B4rh + p * 8192);
            const float4* s2p = (const float4*)(g_B4ih + p * 8192);
#pragma unroll
            for (int t = 0; t < 4; ++t) {
                ((float4*)(smem + 16384))[tid + 128 * t] = s0[tid + 128 * t];
                ((float4*)(smem + 24576))[tid + 128 * t] = s2p[tid + 128 * t];
            }
        }
        __syncthreads();

        float acc[2][2][4] = {};    // [mt][nt_local]
#pragma unroll
        for (int ri = 0; ri < 2; ++ri) {
#pragma unroll
            for (int kk = 0; kk < 4; ++kk) {
                u32 ah[2][4], al[2][4];
#pragma unroll
                for (int mt = 0; mt < 2; ++mt) {
                    u32 row = mt * 16 + (lane & 15);
                    u32 blk = kk * 2 + (lane >> 4);
                    u32 off = SW128(row * 128 + blk * 16);
                    ldsm_x4(ah[mt], sA[ri][0] + off);
                    ldsm_x4(al[mt], sA[ri][1] + off);
                }
#pragma unroll
                for (int nt = 0; nt < 2; ++nt) {
                    u32 row = (w * 2 + nt) * 8 + (lane & 7);
                    u32 blk = kk * 2 + ((lane >> 3) & 1);
                    u32 off = SW128(row * 128 + blk * 16);
                    u32 bh[2];
                    ldsm_x2(bh, sB[ri] + off);
#pragma unroll
                    for (int mt = 0; mt < 2; ++mt) {
                        mma_f16(acc[mt][nt], ah[mt], bh);
                        mma_f16(acc[mt][nt], al[mt], bh);
                    }
                }
            }
        }
        // store pass results
#pragma unroll
        for (int nt = 0; nt < 2; ++nt) {
            int nx = p * 64 + (w * 2 + nt) * 8 + 2 * t4;
            size_t base = ((size_t)(b * 512 + nx) * 64 + ky) * 32;
#pragma unroll
            for (int mt = 0; mt < 2; ++mt) {
                int dv1 = mt * 16 + g, dv2 = dv1 + 8;
                g_S4[base + dv1]        = acc[mt][nt][0];
                g_S4[base + 2048 + dv1] = acc[mt][nt][1];
                g_S4[base + dv2]        = acc[mt][nt][2];
                g_S4[base + 2048 + dv2] = acc[mt][nt][3];
            }
        }
        __syncthreads();
    }
}

// ---------------------------------------------------------------------------
// Step 5 (HMMA fp16): per (b, nx-quad): D[m=(a,dv)=128][n=ny], K=ky=64.
// smem: AH@0(16K) AL@16K BH@32K(8K) = 40KB
// ---------------------------------------------------------------------------
__global__ __launch_bounds__(128) void k_step5_mma(float* __restrict__ out) {
    extern __shared__ char smem[];
    u32 sb = smem_u32(smem);
    const u32 sAH = sb, sAL = sb + 16384, sBH = sb + 32768;
    int tid = threadIdx.x, w = tid >> 5, lane = tid & 31;
    int nx0 = blockIdx.x * 4, b = blockIdx.y;

    {
        int mrow = w * 32 + lane;
        const float* s4row = g_S4 + ((size_t)(b * 512 + nx0 + w)) * 64 * 32 + lane;
#pragma unroll 8
        for (int k2 = 0; k2 < 32; ++k2) {
            float v0 = s4row[(2 * k2) * 32];
            float v1 = s4row[(2 * k2 + 1) * 32];
            u32 hp, lp;
            split_pair_f16(v0, v1, hp, lp);
            u32 off = SW128((u32)(mrow * 128 + k2 * 4));
            *(u32*)(smem + off) = hp;
            *(u32*)(smem + 16384 + off) = lp;
        }
    }
    __syncthreads();

    u32 ah[2][4][4], al[2][4][4];
#pragma unroll
    for (int mt = 0; mt < 2; ++mt)
#pragma unroll
        for (int kk = 0; kk < 4; ++kk) {
            u32 row = w * 32 + mt * 16 + (lane & 15);
            u32 blk = kk * 2 + (lane >> 4);
            u32 off = SW128(row * 128 + blk * 16);
            ldsm_x4(ah[mt][kk], sAH + off);
            ldsm_x4(al[mt][kk], sAL + off);
        }

    int g = lane >> 2, t4 = lane & 3;
    float* obase = out + ((size_t)(b * 512 + nx0 + w)) * 512 * 32;

    for (int p = 0; p < 8; ++p) {
        __syncthreads();
        {
            const float4* sh = (const float4*)(g_Bth + p * 8192);
            float4* dh = (float4*)(smem + 32768);
#pragma unroll
            for (int t = 0; t < 4; ++t) dh[tid + 128 * t] = sh[tid + 128 * t];
        }
        __syncthreads();

#pragma unroll
        for (int nt = 0; nt < 8; ++nt) {
            u32 bh[4][2];
#pragma unroll
            for (int kk = 0; kk < 4; ++kk) {
                u32 row = nt * 8 + (lane & 7);
                u32 blk = kk * 2 + ((lane >> 3) & 1);
                u32 off = SW128(row * 128 + blk * 16);
                ldsm_x2(bh[kk], sBH + off);
            }
            float acc[2][4] = {};
#pragma unroll
            for (int kk = 0; kk < 4; ++kk)
#pragma unroll
                for (int mt = 0; mt < 2; ++mt) {
                    mma_f16(acc[mt], ah[mt][kk], bh[kk]);
                    mma_f16(acc[mt], al[mt][kk], bh[kk]);
                }
#pragma unroll
            for (int mt = 0; mt < 2; ++mt) {
                int dv1 = mt * 16 + g, dv2 = dv1 + 8;
                int ny0 = p * 64 + nt * 8 + 2 * t4;
                obase[(size_t)ny0 * 32 + dv1]       = acc[mt][0];
                obase[(size_t)(ny0 + 1) * 32 + dv1] = acc[mt][1];
                obase[(size_t)ny0 * 32 + dv2]       = acc[mt][2];
                obase[(size_t)(ny0 + 1) * 32 + dv2] = acc[mt][3];
            }
        }
    }
}

// ---------------------------------------------------------------------------
extern "C" void kernel_launch(void* const* d_in, const int* in_sizes, int n_in,
                              void* d_out, int out_size) {
    const float* x  = (const float*)d_in[0];
    const float* Rr = (const float*)d_in[1];
    const float* Ri = (const float*)d_in[2];
    float* out = (float*)d_out;

    k_precompute<<<128, 256>>>();
    k_step1_mma<<<dim3(128, BB), 128, 40960>>>(x);
    k_step2n<<<dim3(64, BB), 128, 24576>>>();
    k_step3<<<dim3(KXX, KYY / 16, 8), 256>>>(Rr, Ri);
    k_step4n<<<dim3(64, BB), 128, 32768>>>();
    k_step5_mma<<<dim3(128, BB), 128, 40960>>>(out);
}